// round 13
// baseline (speedup 1.0000x reference)
#include <cuda_runtime.h>

#define BN 256
#define TN 512
#define CN 128
#define FN 128
#define NB 32
#define VS 34      /* Vp row stride (even -> 8B-aligned col pairs) */

typedef unsigned long long ull;

__device__ float g_scratch[(size_t)BN * TN * FN];   // 64 MB scratch

__device__ __forceinline__ ull pk2(float lo, float hi) {
    ull r; asm("mov.b64 %0, {%1, %2};" : "=l"(r) : "f"(lo), "f"(hi)); return r;
}
__device__ __forceinline__ void upk2(ull v, float& lo, float& hi) {
    asm("mov.b64 {%0, %1}, %2;" : "=f"(lo), "=f"(hi) : "l"(v));
}
__device__ __forceinline__ ull fma2(ull a, ull b, ull c) {
    ull d; asm("fma.rn.f32x2 %0, %1, %2, %3;" : "=l"(d) : "l"(a), "l"(b), "l"(c)); return d;
}
__device__ __forceinline__ ull mul2(ull a, ull b) {
    ull d; asm("mul.rn.f32x2 %0, %1, %2;" : "=l"(d) : "l"(a), "l"(b)); return d;
}
__device__ __forceinline__ float wsum(float v) {
    #pragma unroll
    for (int o = 16; o; o >>= 1) v += __shfl_xor_sync(0xffffffffu, v, o);
    return v;
}

// ============================================================
// Fused conv + geqrf + R^{-1} + (Q = Y * Rinv), one CTA per batch matrix.
// ============================================================
#define VP(t,i)   Vp[(t) * VS + (i)]
#define W2STRIDE  120
#define RGS       130   /* Rinv SMEM row stride (phase 3) */

template<int WT>
__device__ void block_apply(float* __restrict__ G, int o, int colbase,
                            const float* __restrict__ Vp, const float* __restrict__ Tp,
                            float* __restrict__ Wm, float* __restrict__ Wm2, int tid)
{
    const int lane = tid & 31, w = tid >> 5;
    constexpr int NU = WT / 32;
    constexpr int HW = WT / 2;
    constexpr int TU = 32 * HW;
    ull* Gs = (ull*)Wm2;

    // GEMM1: Wm[i][c] = sum_t V[t][i]*G[t][colbase+c]
    ull acc[NU];
    #pragma unroll
    for (int k = 0; k < NU; k++) acc[k] = 0ull;
    const int ntiles = (TN - o) >> 5;
    for (int tile = 0; tile < ntiles; tile++) {
        const int t0 = o + (tile << 5);
        #pragma unroll
        for (int u = tid; u < TU; u += 512) {
            int r = u / HW, c = u - r * HW;
            Gs[u] = *(const ull*)(G + (size_t)(t0 + r) * FN + colbase + 2 * c);
        }
        __syncthreads();
        #pragma unroll
        for (int r = 0; r < 32; r++) {
            float v = VP(t0 + r, lane);
            ull vv = pk2(v, v);
            const ull* g = Gs + r * HW + w * NU;
            #pragma unroll
            for (int k = 0; k < NU; k++) acc[k] = fma2(vv, g[k], acc[k]);
        }
        __syncthreads();
    }
    {
        ull* wout = (ull*)(Wm + lane * 96) + w * NU;
        #pragma unroll
        for (int k = 0; k < NU; k++) wout[k] = acc[k];
    }
    __syncthreads();

    // Tapply: Wm2 = -(T^T * Wm), group-10 padded
    {
        constexpr int NCG = WT / 8;
        for (int pos = tid; pos < 32 * NCG * 4; pos += 512) {
            int i = pos / (NCG * 4);
            int rem = pos - i * (NCG * 4);
            int cg = rem >> 2, k = rem & 3;
            int c = cg * 8 + 2 * k;
            ull a = 0ull;
            #pragma unroll
            for (int j = 0; j < 32; j++) {
                float tv = Tp[j * 33 + i];
                a = fma2(pk2(-tv, -tv), *(const ull*)(Wm + j * 96 + c), a);
            }
            *(ull*)(Wm2 + i * W2STRIDE + cg * 10 + 2 * k) = a;
        }
    }
    __syncthreads();

    // GEMM2: G += V * Wm2
    {
        constexpr int NCG = WT / 8;
        const int npos = ((TN - o) >> 2) * NCG;
        for (int pos = tid; pos < npos; pos += 512) {
            int tg = pos / NCG, cg = pos - tg * NCG;
            int t0 = o + (tg << 2);
            float* gp = G + (size_t)t0 * FN + colbase + cg * 8;
            ull a[4][4];
            #pragma unroll
            for (int r = 0; r < 4; r++) {
                ulonglong2 q0 = ((const ulonglong2*)(gp + r * FN))[0];
                ulonglong2 q1 = ((const ulonglong2*)(gp + r * FN))[1];
                a[r][0] = q0.x; a[r][1] = q0.y; a[r][2] = q1.x; a[r][3] = q1.y;
            }
            const float* vr0 = Vp + (size_t)t0 * VS;
            const float* vr1 = vr0 + VS;
            const float* vr2 = vr1 + VS;
            const float* vr3 = vr2 + VS;
            const float* w2base = Wm2 + cg * 10;
            #pragma unroll 4
            for (int i = 0; i < 32; i++) {
                const ull* wp = (const ull*)(w2base + i * W2STRIDE);
                ull w0 = wp[0], w1 = wp[1], w2 = wp[2], w3 = wp[3];
                float v0 = vr0[i], v1 = vr1[i], v2 = vr2[i], v3 = vr3[i];
                ull vv0 = pk2(v0, v0), vv1 = pk2(v1, v1);
                ull vv2 = pk2(v2, v2), vv3 = pk2(v3, v3);
                a[0][0] = fma2(vv0, w0, a[0][0]); a[0][1] = fma2(vv0, w1, a[0][1]);
                a[0][2] = fma2(vv0, w2, a[0][2]); a[0][3] = fma2(vv0, w3, a[0][3]);
                a[1][0] = fma2(vv1, w0, a[1][0]); a[1][1] = fma2(vv1, w1, a[1][1]);
                a[1][2] = fma2(vv1, w2, a[1][2]); a[1][3] = fma2(vv1, w3, a[1][3]);
                a[2][0] = fma2(vv2, w0, a[2][0]); a[2][1] = fma2(vv2, w1, a[2][1]);
                a[2][2] = fma2(vv2, w2, a[2][2]); a[2][3] = fma2(vv2, w3, a[2][3]);
                a[3][0] = fma2(vv3, w0, a[3][0]); a[3][1] = fma2(vv3, w1, a[3][1]);
                a[3][2] = fma2(vv3, w2, a[3][2]); a[3][3] = fma2(vv3, w3, a[3][3]);
            }
            #pragma unroll
            for (int r = 0; r < 4; r++) {
                ulonglong2 q0, q1;
                q0.x = a[r][0]; q0.y = a[r][1]; q1.x = a[r][2]; q1.y = a[r][3];
                ((ulonglong2*)(gp + r * FN))[0] = q0;
                ((ulonglong2*)(gp + r * FN))[1] = q1;
            }
        }
    }
    __syncthreads();
}

// Packed panel factorization: 2 barriers/column; phase A and C use f32x2.
__device__ void panel_factor(float* Vp, float* taus, float* betas,
                             float* wred, float* rowp, int o, int tid)
{
    const int lane = tid & 31, w = tid >> 5;
    const int ca = 2 * w;
    const int half = lane >> 4;
    const int cl2 = (lane & 15) * 2;

    for (int i = 0; i < NB; i++) {
        const int prow = o + i;
        if (w == 0) rowp[lane] = VP(prow, lane);
        ull acc = 0ull;
        #pragma unroll 2
        for (int t = prow + lane; t < TN; t += 32) {
            float vi = VP(t, i);
            ull pr = *(const ull*)&VP(t, ca);
            acc = fma2(pk2(vi, vi), pr, acc);
        }
        float p0, p1; upk2(acc, p0, p1);
        p0 = wsum(p0); p1 = wsum(p1);
        if (lane == 0) { wred[ca] = p0; wred[ca + 1] = p1; }
        __syncthreads();
        float alpha = rowp[i];
        float s2 = wred[i];
        float xn2 = s2 - alpha * alpha;
        float tau, sc, beta;
        if (xn2 <= 0.f) { tau = 0.f; sc = 0.f; beta = alpha; }
        else {
            beta = -copysignf(sqrtf(s2), alpha);
            tau  = (beta - alpha) / beta;
            sc   = 1.f / (alpha - beta);
        }
        if (tid == 0) { taus[i] = tau; betas[i] = beta; }
        if (w == 0) {
            float cjp  = rowp[lane];
            float coef = tau * (cjp + (wred[lane] - alpha * cjp) * sc);
            float nv = (lane == i) ? 1.f : cjp - coef;
            if (lane >= i) VP(prow, lane) = nv;
        }
        {
            int c0 = cl2, c1 = cl2 + 1;
            float cj0 = rowp[c0], cj1 = rowp[c1];
            float cf0 = tau * (cj0 + (wred[c0] - alpha * cj0) * sc);
            float cf1 = tau * (cj1 + (wred[c1] - alpha * cj1) * sc);
            float a0 = (c0 > i) ? -cf0 : (c0 == i ? 1.f : 0.f);
            float b0 = (c0 == i) ? 0.f : 1.f;
            float a1 = (c1 > i) ? -cf1 : (c1 == i ? 1.f : 0.f);
            float b1 = (c1 == i) ? 0.f : 1.f;
            ull ap = pk2(a0, a1), bp = pk2(b0, b1);
            for (int t = prow + 1 + 2 * w + half; t < TN; t += 32) {
                float xt = VP(t, i);
                float vt = xt * sc;
                ull cur = *(const ull*)&VP(t, cl2);
                ull nv  = fma2(pk2(vt, vt), ap, mul2(bp, cur));
                *(ull*)&VP(t, cl2) = nv;
            }
        }
        __syncthreads();
    }
}

__device__ void build_T(const float* Vp, float* B, float* Tp, const float* taus,
                        int o, int tid)
{
    const int lane = tid & 31, w = tid >> 5;
    for (int i = 1; i < NB; i++) {
        for (int j = w; j < i; j += 16) {
            float p = 0.f;
            for (int t = o + i + lane; t < TN; t += 32)
                p += VP(t, j) * VP(t, i);
            p = wsum(p);
            if (lane == 0) B[j * 32 + i] = p;
        }
    }
    __syncthreads();
    if (w == 0) {
        for (int i = 0; i < NB; i++) {
            float ti = taus[i];
            float a = 0.f;
            for (int k = 0; k < i; k++)
                a += Tp[lane * 33 + k] * B[k * 32 + i];
            float tv = (lane < i) ? -ti * a : (lane == i ? ti : 0.f);
            Tp[lane * 33 + i] = tv;
            __syncwarp();
        }
    }
    __syncthreads();
}

// SMEM (floats): Vp 17408 | Tp 1056 | Wm 3072 | Wm2 3840 | taus 32 | betas 32 | wred 32 | rowp 32 = 25504
// Conv overlay (phase 0): Xs 128x33 (4224) | Ws 32x128 (4096) -> 8320 (inside Vp region)
// Phase 2 overlay: Rsm 128x130 (16640) | rd 128
// Phase 3 overlay: Rg 128x130 (16640)  | Ys 128x66 (8448) -> 25088
#define SM_FLOATS 25504
#define SM_BYTES  (SM_FLOATS * 4)

__global__ __launch_bounds__(512, 2) void qr_kernel(
    const float* __restrict__ x, const float* __restrict__ Wc,
    const float* __restrict__ bias, float* __restrict__ Yq)
{
    extern __shared__ float sm[];
    float* Vp    = sm;                 // 17408
    float* Tp    = Vp + 17408;         // 1056
    float* Wm    = Tp + 1056;          // 3072
    float* Wm2   = Wm + 3072;          // 3840 (also GEMM1 staging + build_T B)
    float* taus  = Wm2 + 3840;         // 32
    float* betas = taus + 32;          // 32
    float* wred  = betas + 32;         // 32
    float* rowp  = wred + 32;          // 32

    const int b = blockIdx.x;
    float* G = g_scratch + (size_t)b * TN * FN;
    float* Y = Yq + (size_t)b * TN * FN;
    const int tid = threadIdx.x;
    const int lane = tid & 31, w = tid >> 5;

    // ================ Phase 0: Conv1D for this batch ================
    {
        float* Xs = sm;            // [128][33]
        float* Ws = sm + 4224;     // [32][128]
        const int cbase = lane * 4, rbase = w * 8;
        float b0 = bias[cbase], b1 = bias[cbase + 1],
              b2 = bias[cbase + 2], b3 = bias[cbase + 3];

        for (int tile = 0; tile < 4; tile++) {
            const int t0 = tile * 128;
            ull acc2[8][2];
            #pragma unroll
            for (int i = 0; i < 8; i++) { acc2[i][0] = 0ull; acc2[i][1] = 0ull; }

            for (int k = 0; k < 3; k++) {
                for (int c0 = 0; c0 < CN; c0 += 32) {
                    #pragma unroll
                    for (int q = 0; q < 8; q++) {
                        int e = tid + 512 * q, f = e & 127, cc = e >> 7;
                        Ws[cc * 128 + f] = Wc[((size_t)(k * CN + c0 + cc)) * FN + f];
                    }
                    #pragma unroll
                    for (int q = 0; q < 8; q++) {
                        int e = tid + 512 * q, cc = e & 31, r = e >> 5;
                        int t = t0 + r + k - 1;
                        float v = 0.f;
                        if (t >= 0 && t < TN)
                            v = x[((size_t)b * TN + t) * CN + c0 + cc];
                        Xs[r * 33 + cc] = v;
                    }
                    __syncthreads();
                    #pragma unroll
                    for (int cc = 0; cc < 32; cc++) {
                        const ull* wp = (const ull*)&Ws[cc * 128 + cbase];
                        ull w01 = wp[0], w23 = wp[1];
                        #pragma unroll
                        for (int i = 0; i < 8; i++) {
                            float xv = Xs[(rbase + i) * 33 + cc];
                            ull xx = pk2(xv, xv);
                            acc2[i][0] = fma2(xx, w01, acc2[i][0]);
                            acc2[i][1] = fma2(xx, w23, acc2[i][1]);
                        }
                    }
                    __syncthreads();
                }
            }
            #pragma unroll
            for (int i = 0; i < 8; i++) {
                int t = t0 + rbase + i;
                float4 o; float lo, hi;
                upk2(acc2[i][0], lo, hi); o.x = lo + b0; o.y = hi + b1;
                upk2(acc2[i][1], lo, hi); o.z = lo + b2; o.w = hi + b3;
                size_t off = (size_t)t * FN + cbase;
                *(float4*)&Y[off] = o;
                *(float4*)&G[off] = o;
            }
        }
        __syncthreads();   // Y/G complete before geqrf; Xs/Ws overlay freed
    }

    // ================ Phase 1: geqrf (blocked, trailing only) ================
    for (int p = 0; p < 4; p++) {
        const int o = p * 32;
        for (int t = o + w; t < TN; t += 16)
            VP(t, lane) = G[(size_t)t * FN + o + lane];
        __syncthreads();
        panel_factor(Vp, taus, betas, wred, rowp, o, tid);
        for (int pos = tid; pos < 32 * 32; pos += 512) {
            int r = pos >> 5, i = pos & 31;
            float val = (r < i) ? VP(o + r, i) : (r == i ? betas[i] : 0.f);
            G[(size_t)(o + r) * FN + o + i] = val;
        }
        __syncthreads();
        if (p < 3) {
            for (int pos = tid; pos < 32 * 32; pos += 512) {
                int i = pos >> 5, r = pos & 31;
                if (r < i) VP(o + r, i) = 0.f;
            }
            __syncthreads();
            build_T(Vp, Wm2, Tp, taus, o, tid);
            if (p == 0)      block_apply<96>(G, 0,  32, Vp, Tp, Wm, Wm2, tid);
            else if (p == 1) block_apply<64>(G, 32, 64, Vp, Tp, Wm, Wm2, tid);
            else             block_apply<32>(G, 64, 96, Vp, Tp, Wm, Wm2, tid);
        }
    }
    __syncthreads();

    // ================ Phase 2: R^{-1} with 8-column ILP per warp ================
    float* Rsm = sm;             // 128 x 130 (overlays Vp)
    float* rd  = sm + 16640;     // 128 reciprocals
    for (int e = tid; e < 128 * 128; e += 512) {
        int r = e >> 7, c = e & 127;
        Rsm[r * 130 + c] = G[(size_t)r * FN + c];
    }
    __syncthreads();
    if (tid < 128) rd[tid] = 1.f / Rsm[tid * 130 + tid];
    __syncthreads();

    float xr[8][4];   // warp w owns columns c = w + 16m
    #pragma unroll
    for (int m = 0; m < 8; m++) {
        #pragma unroll
        for (int q = 0; q < 4; q++) xr[m][q] = 0.f;
        int c = w + (m << 4);
        float dv = rd[c];
        if ((c & 31) == lane) {
            int q = c >> 5;
            if (q == 0) xr[m][0] = dv; else if (q == 1) xr[m][1] = dv;
            else if (q == 2) xr[m][2] = dv; else xr[m][3] = dv;
        }
    }
    for (int k = 126; k >= 0; k--) {
        const float* Rk = Rsm + k * 130;
        float r0 = Rk[lane], r1 = Rk[lane + 32], r2 = Rk[lane + 64], r3 = Rk[lane + 96];
        float rk = rd[k];
        int qk = k >> 5, lk = k & 31;
        #pragma unroll
        for (int m = 0; m < 8; m++) {
            int c = w + (m << 4);
            if (c > k) {
                float s = r0 * xr[m][0] + r1 * xr[m][1] + r2 * xr[m][2] + r3 * xr[m][3];
                s = wsum(s);
                float xk = -s * rk;
                if (lk == lane) {
                    if (qk == 0) xr[m][0] = xk; else if (qk == 1) xr[m][1] = xk;
                    else if (qk == 2) xr[m][2] = xk; else xr[m][3] = xk;
                }
            }
        }
    }
    __syncthreads();   // all solve reads of Rsm complete

    // Rinv -> SMEM (stride-130, reads are warp-uniform)
    float* Rg = sm;              // 128 x 130 (in place of Rsm)
    float* Ys = sm + 16640;      // 128 x 66
    #pragma unroll
    for (int m = 0; m < 8; m++) {
        int c = w + (m << 4);
        float* dst = Rg + c;
        dst[(size_t)lane * RGS]        = xr[m][0];
        dst[(size_t)(lane + 32) * RGS] = xr[m][1];
        dst[(size_t)(lane + 64) * RGS] = xr[m][2];
        dst[(size_t)(lane + 96) * RGS] = xr[m][3];
    }
    __syncthreads();

    // ================ Phase 3: Q = Y * Rinv (8 tiles of 64 rows) ================
    const int cA = 4 * w, cB = 124 - 4 * w;
    const int kmaxA = cA + 4, kmaxB = cB + 4;
    const float* RgA = Rg + cA;
    const float* RgB = Rg + cB;

    for (int tile = 0; tile < 8; tile++) {
        const int t0 = tile * 64;
        #pragma unroll
        for (int e = tid; e < 64 * 32; e += 512) {
            int r = e >> 5, g4 = e & 31;
            float4 v = *(const float4*)(Y + (size_t)(t0 + r) * FN + g4 * 4);
            float* dst = Ys + (g4 * 4) * 66 + r;
            dst[0] = v.x; dst[66] = v.y; dst[132] = v.z; dst[198] = v.w;
        }
        __syncthreads();

        ull aA0 = 0ull, aA1 = 0ull, aB0 = 0ull, aB1 = 0ull;
        ull bA0 = 0ull, bA1 = 0ull, bB0 = 0ull, bB1 = 0ull;
        const float* yb0 = Ys + lane;
        const float* yb1 = Ys + lane + 32;
        int k = 0;
        for (; k < kmaxA; k++) {
            float y0 = yb0[k * 66], y1 = yb1[k * 66];
            ull v0 = pk2(y0, y0), v1 = pk2(y1, y1);
            const ull* wa = (const ull*)(RgA + k * RGS);
            const ull* wb = (const ull*)(RgB + k * RGS);
            ull wa0 = wa[0], wa1 = wa[1], wb0 = wb[0], wb1 = wb[1];
            aA0 = fma2(v0, wa0, aA0); aA1 = fma2(v0, wa1, aA1);
            aB0 = fma2(v0, wb0, aB0); aB1 = fma2(v0, wb1, aB1);
            bA0 = fma2(v1, wa0, bA0); bA1 = fma2(v1, wa1, bA1);
            bB0 = fma2(v1, wb0, bB0); bB1 = fma2(v1, wb1, bB1);
        }
        for (; k < kmaxB; k++) {
            float y0 = yb0[k * 66], y1 = yb1[k * 66];
            ull v0 = pk2(y0, y0), v1 = pk2(y1, y1);
            const ull* wb = (const ull*)(RgB + k * RGS);
            ull wb0 = wb[0], wb1 = wb[1];
            aB0 = fma2(v0, wb0, aB0); aB1 = fma2(v0, wb1, aB1);
            bB0 = fma2(v1, wb0, bB0); bB1 = fma2(v1, wb1, bB1);
        }
        __syncthreads();

        float* orow0 = Y + (size_t)(t0 + lane) * FN;
        float* orow1 = Y + (size_t)(t0 + lane + 32) * FN;
        ulonglong2 q;
        q.x = aA0; q.y = aA1; *(ulonglong2*)(orow0 + cA) = q;
        q.x = aB0; q.y = aB1; *(ulonglong2*)(orow0 + cB) = q;
        q.x = bA0; q.y = bA1; *(ulonglong2*)(orow1 + cA) = q;
        q.x = bB0; q.y = bB1; *(ulonglong2*)(orow1 + cB) = q;
    }
}

// ============================================================
extern "C" void kernel_launch(void* const* d_in, const int* in_sizes, int n_in,
                              void* d_out, int out_size)
{
    const float* x    = (const float*)d_in[0];
    const float* W    = (const float*)d_in[1];
    const float* bias = (const float*)d_in[2];
    float* out = (float*)d_out;

    cudaFuncSetAttribute(qr_kernel, cudaFuncAttributeMaxDynamicSharedMemorySize, SM_BYTES);

    qr_kernel<<<BN, 512, SM_BYTES>>>(x, W, bias, out);   // conv + geqrf + Rinv + Q
}

// round 14
// speedup vs baseline: 1.1178x; 1.1178x over previous
#include <cuda_runtime.h>

#define BN 256
#define TN 512
#define CN 128
#define FN 128
#define NB 32
#define VS 34      /* Vp row stride (even -> 8B-aligned col pairs) */

typedef unsigned long long ull;

__device__ float g_scratch[(size_t)BN * TN * FN];   // 64 MB scratch

__device__ __forceinline__ ull pk2(float lo, float hi) {
    ull r; asm("mov.b64 %0, {%1, %2};" : "=l"(r) : "f"(lo), "f"(hi)); return r;
}
__device__ __forceinline__ void upk2(ull v, float& lo, float& hi) {
    asm("mov.b64 {%0, %1}, %2;" : "=f"(lo), "=f"(hi) : "l"(v));
}
__device__ __forceinline__ ull fma2(ull a, ull b, ull c) {
    ull d; asm("fma.rn.f32x2 %0, %1, %2, %3;" : "=l"(d) : "l"(a), "l"(b), "l"(c)); return d;
}
__device__ __forceinline__ ull mul2(ull a, ull b) {
    ull d; asm("mul.rn.f32x2 %0, %1, %2;" : "=l"(d) : "l"(a), "l"(b)); return d;
}
__device__ __forceinline__ float wsum(float v) {
    #pragma unroll
    for (int o = 16; o; o >>= 1) v += __shfl_xor_sync(0xffffffffu, v, o);
    return v;
}

// ============================================================
// Conv1D (256 threads, 8 rows x 4 cols/thread — proven fastest variant).
// Writes y to BOTH d_out (preserved Y) and scratch (working copy).
// ============================================================
__global__ __launch_bounds__(256) void conv_kernel(
    const float* __restrict__ x, const float* __restrict__ W,
    const float* __restrict__ bias, float* __restrict__ y)
{
    __shared__ float Xs[64][33];
    __shared__ float Ws[32][128];

    const int b = blockIdx.y, t0 = blockIdx.x * 64, tid = threadIdx.x;
    const int lane = tid & 31, warp = tid >> 5;
    const int cbase = lane * 4, rbase = warp * 8;

    ull acc2[8][2];
    #pragma unroll
    for (int i = 0; i < 8; i++) { acc2[i][0] = 0ull; acc2[i][1] = 0ull; }

    for (int k = 0; k < 3; k++) {
        for (int c0 = 0; c0 < CN; c0 += 32) {
            #pragma unroll
            for (int q = 0; q < 16; q++) {
                int e = tid + 256 * q, f = e & 127, cc = e >> 7;
                Ws[cc][f] = W[((size_t)(k * CN + c0 + cc)) * FN + f];
            }
            #pragma unroll
            for (int q = 0; q < 8; q++) {
                int e = tid + 256 * q, cc = e & 31, r = e >> 5;
                int t = t0 + r + k - 1;
                float v = 0.f;
                if (t >= 0 && t < TN) v = x[((size_t)b * TN + t) * CN + c0 + cc];
                Xs[r][cc] = v;
            }
            __syncthreads();
            #pragma unroll
            for (int cc = 0; cc < 32; cc++) {
                const ull* wp = (const ull*)&Ws[cc][cbase];
                ull w01 = wp[0], w23 = wp[1];
                #pragma unroll
                for (int i = 0; i < 8; i++) {
                    float xv = Xs[rbase + i][cc];
                    ull xx = pk2(xv, xv);
                    acc2[i][0] = fma2(xx, w01, acc2[i][0]);
                    acc2[i][1] = fma2(xx, w23, acc2[i][1]);
                }
            }
            __syncthreads();
        }
    }
    float b0 = bias[cbase], b1 = bias[cbase+1], b2 = bias[cbase+2], b3 = bias[cbase+3];
    #pragma unroll
    for (int i = 0; i < 8; i++) {
        int t = t0 + rbase + i;
        float4 o; float lo, hi;
        upk2(acc2[i][0], lo, hi); o.x = lo + b0; o.y = hi + b1;
        upk2(acc2[i][1], lo, hi); o.z = lo + b2; o.w = hi + b3;
        size_t off = ((size_t)b * TN + t) * FN + cbase;
        *(float4*)&y[off] = o;
        *(float4*)&g_scratch[off] = o;
    }
}

// ============================================================
// Fused geqrf + R^{-1} + (Q = Y * Rinv), one CTA per 512x128 matrix.
// ============================================================
#define VP(t,i)   Vp[(t) * VS + (i)]
#define W2STRIDE  120
#define RGS       130   /* Rinv SMEM row stride (phase 3) */

template<int WT>
__device__ void block_apply(float* __restrict__ G, int o, int colbase,
                            const float* __restrict__ Vp, const float* __restrict__ Tp,
                            float* __restrict__ Wm, float* __restrict__ Wm2, int tid)
{
    const int lane = tid & 31, w = tid >> 5;
    constexpr int NU = WT / 32;
    constexpr int HW = WT / 2;
    constexpr int TU = 32 * HW;
    ull* Gs = (ull*)Wm2;

    // GEMM1: Wm[i][c] = sum_t V[t][i]*G[t][colbase+c]
    ull acc[NU];
    #pragma unroll
    for (int k = 0; k < NU; k++) acc[k] = 0ull;
    const int ntiles = (TN - o) >> 5;
    for (int tile = 0; tile < ntiles; tile++) {
        const int t0 = o + (tile << 5);
        #pragma unroll
        for (int u = tid; u < TU; u += 512) {
            int r = u / HW, c = u - r * HW;
            Gs[u] = *(const ull*)(G + (size_t)(t0 + r) * FN + colbase + 2 * c);
        }
        __syncthreads();
        #pragma unroll
        for (int r = 0; r < 32; r++) {
            float v = VP(t0 + r, lane);
            ull vv = pk2(v, v);
            const ull* g = Gs + r * HW + w * NU;
            #pragma unroll
            for (int k = 0; k < NU; k++) acc[k] = fma2(vv, g[k], acc[k]);
        }
        __syncthreads();
    }
    {
        ull* wout = (ull*)(Wm + lane * 96) + w * NU;
        #pragma unroll
        for (int k = 0; k < NU; k++) wout[k] = acc[k];
    }
    __syncthreads();

    // Tapply: Wm2 = -(T^T * Wm), group-10 padded
    {
        constexpr int NCG = WT / 8;
        for (int pos = tid; pos < 32 * NCG * 4; pos += 512) {
            int i = pos / (NCG * 4);
            int rem = pos - i * (NCG * 4);
            int cg = rem >> 2, k = rem & 3;
            int c = cg * 8 + 2 * k;
            ull a = 0ull;
            #pragma unroll
            for (int j = 0; j < 32; j++) {
                float tv = Tp[j * 33 + i];
                a = fma2(pk2(-tv, -tv), *(const ull*)(Wm + j * 96 + c), a);
            }
            *(ull*)(Wm2 + i * W2STRIDE + cg * 10 + 2 * k) = a;
        }
    }
    __syncthreads();

    // GEMM2: G += V * Wm2
    {
        constexpr int NCG = WT / 8;
        const int npos = ((TN - o) >> 2) * NCG;
        for (int pos = tid; pos < npos; pos += 512) {
            int tg = pos / NCG, cg = pos - tg * NCG;
            int t0 = o + (tg << 2);
            float* gp = G + (size_t)t0 * FN + colbase + cg * 8;
            ull a[4][4];
            #pragma unroll
            for (int r = 0; r < 4; r++) {
                ulonglong2 q0 = ((const ulonglong2*)(gp + r * FN))[0];
                ulonglong2 q1 = ((const ulonglong2*)(gp + r * FN))[1];
                a[r][0] = q0.x; a[r][1] = q0.y; a[r][2] = q1.x; a[r][3] = q1.y;
            }
            const float* vr0 = Vp + (size_t)t0 * VS;
            const float* vr1 = vr0 + VS;
            const float* vr2 = vr1 + VS;
            const float* vr3 = vr2 + VS;
            const float* w2base = Wm2 + cg * 10;
            #pragma unroll 4
            for (int i = 0; i < 32; i++) {
                const ull* wp = (const ull*)(w2base + i * W2STRIDE);
                ull w0 = wp[0], w1 = wp[1], w2 = wp[2], w3 = wp[3];
                float v0 = vr0[i], v1 = vr1[i], v2 = vr2[i], v3 = vr3[i];
                ull vv0 = pk2(v0, v0), vv1 = pk2(v1, v1);
                ull vv2 = pk2(v2, v2), vv3 = pk2(v3, v3);
                a[0][0] = fma2(vv0, w0, a[0][0]); a[0][1] = fma2(vv0, w1, a[0][1]);
                a[0][2] = fma2(vv0, w2, a[0][2]); a[0][3] = fma2(vv0, w3, a[0][3]);
                a[1][0] = fma2(vv1, w0, a[1][0]); a[1][1] = fma2(vv1, w1, a[1][1]);
                a[1][2] = fma2(vv1, w2, a[1][2]); a[1][3] = fma2(vv1, w3, a[1][3]);
                a[2][0] = fma2(vv2, w0, a[2][0]); a[2][1] = fma2(vv2, w1, a[2][1]);
                a[2][2] = fma2(vv2, w2, a[2][2]); a[2][3] = fma2(vv2, w3, a[2][3]);
                a[3][0] = fma2(vv3, w0, a[3][0]); a[3][1] = fma2(vv3, w1, a[3][1]);
                a[3][2] = fma2(vv3, w2, a[3][2]); a[3][3] = fma2(vv3, w3, a[3][3]);
            }
            #pragma unroll
            for (int r = 0; r < 4; r++) {
                ulonglong2 q0, q1;
                q0.x = a[r][0]; q0.y = a[r][1]; q1.x = a[r][2]; q1.y = a[r][3];
                ((ulonglong2*)(gp + r * FN))[0] = q0;
                ((ulonglong2*)(gp + r * FN))[1] = q1;
            }
        }
    }
    __syncthreads();
}

// Panel factorization: packed phase-A dots, row-per-thread phase C with
// pre-negated packed coefficients (only live columns touched).
__device__ void panel_factor(float* Vp, float* taus, float* betas,
                             float* wred, float* rowp, float* ncoefs,
                             int o, int tid)
{
    const int lane = tid & 31, w = tid >> 5;
    const int ca = 2 * w;

    for (int i = 0; i < NB; i++) {
        const int prow = o + i;
        if (w == 0) rowp[lane] = VP(prow, lane);
        // ---- Phase A: packed dots s_j = sum_{t>=prow} x_t * c_j[t] ----
        ull acc = 0ull;
        #pragma unroll 2
        for (int t = prow + lane; t < TN; t += 32) {
            float vi = VP(t, i);
            ull pr = *(const ull*)&VP(t, ca);
            acc = fma2(pk2(vi, vi), pr, acc);
        }
        float p0, p1; upk2(acc, p0, p1);
        p0 = wsum(p0); p1 = wsum(p1);
        if (lane == 0) { wred[ca] = p0; wred[ca + 1] = p1; }
        __syncthreads();
        // redundant scalar compute (all threads)
        float alpha = rowp[i];
        float s2 = wred[i];
        float xn2 = s2 - alpha * alpha;
        float tau, sc, beta;
        if (xn2 <= 0.f) { tau = 0.f; sc = 0.f; beta = alpha; }
        else {
            beta = -copysignf(sqrtf(s2), alpha);
            tau  = (beta - alpha) / beta;
            sc   = 1.f / (alpha - beta);
        }
        if (tid == 0) { taus[i] = tau; betas[i] = beta; }
        // warp 0: publish negated coefs + write row prow
        if (w == 0) {
            float cjp  = rowp[lane];
            float coef = tau * (cjp + (wred[lane] - alpha * cjp) * sc);
            ncoefs[lane] = -coef;
            float nv = (lane == i) ? 1.f : cjp - coef;
            if (lane >= i) VP(prow, lane) = nv;
        }
        __syncthreads();   // coefs ready
        // ---- Phase C: one row per thread, live columns only ----
        int t = prow + 1 + tid;
        if (t < TN) {
            float* vr = Vp + (size_t)t * VS;
            float xt = vr[i];
            float vt = xt * sc;
            vr[i] = vt;
            int j = i + 1;
            if (j < NB) {
                if (j & 1) { vr[j] = fmaf(ncoefs[j], vt, vr[j]); j++; }
                ull vt2 = pk2(vt, vt);
                for (; j < NB; j += 2) {
                    ull nc  = *(const ull*)&ncoefs[j];
                    ull cur = *(const ull*)&vr[j];
                    *(ull*)&vr[j] = fma2(vt2, nc, cur);
                }
            }
        }
        __syncthreads();
    }
}

__device__ void build_T(const float* Vp, float* B, float* Tp, const float* taus,
                        int o, int tid)
{
    const int lane = tid & 31, w = tid >> 5;
    for (int i = 1; i < NB; i++) {
        for (int j = w; j < i; j += 16) {
            float p = 0.f;
            for (int t = o + i + lane; t < TN; t += 32)
                p += VP(t, j) * VP(t, i);
            p = wsum(p);
            if (lane == 0) B[j * 32 + i] = p;
        }
    }
    __syncthreads();
    if (w == 0) {
        for (int i = 0; i < NB; i++) {
            float ti = taus[i];
            float a = 0.f;
            for (int k = 0; k < i; k++)
                a += Tp[lane * 33 + k] * B[k * 32 + i];
            float tv = (lane < i) ? -ti * a : (lane == i ? ti : 0.f);
            Tp[lane * 33 + i] = tv;
            __syncwarp();
        }
    }
    __syncthreads();
}

// SMEM (floats): Vp 17408 | Tp 1056 | Wm 3072 | Wm2 3840 | taus 32 | betas 32 | wred 32 | rowp 32 | ncoefs 32 = 25536
// Phase 2 overlay: Rsm 128x130 (16640) | rd 128
// Phase 3 overlay: Rg 128x130 (16640)  | Ys 128x66 (8448) -> 25088
#define SM_FLOATS 25536
#define SM_BYTES  (SM_FLOATS * 4)

__global__ __launch_bounds__(512, 2) void qr_kernel(float* __restrict__ Yq)
{
    extern __shared__ float sm[];
    float* Vp     = sm;                 // 17408
    float* Tp     = Vp + 17408;         // 1056
    float* Wm     = Tp + 1056;          // 3072
    float* Wm2    = Wm + 3072;          // 3840 (also GEMM1 staging + build_T B)
    float* taus   = Wm2 + 3840;         // 32
    float* betas  = taus + 32;          // 32
    float* wred   = betas + 32;         // 32
    float* rowp   = wred + 32;          // 32
    float* ncoefs = rowp + 32;          // 32

    const int b = blockIdx.x;
    float* G = g_scratch + (size_t)b * TN * FN;
    float* Y = Yq + (size_t)b * TN * FN;
    const int tid = threadIdx.x;
    const int lane = tid & 31, w = tid >> 5;

    // ---------------- geqrf (blocked, trailing only) ----------------
    for (int p = 0; p < 4; p++) {
        const int o = p * 32;
        for (int t = o + w; t < TN; t += 16)
            VP(t, lane) = G[(size_t)t * FN + o + lane];
        __syncthreads();
        panel_factor(Vp, taus, betas, wred, rowp, ncoefs, o, tid);
        for (int pos = tid; pos < 32 * 32; pos += 512) {
            int r = pos >> 5, i = pos & 31;
            float val = (r < i) ? VP(o + r, i) : (r == i ? betas[i] : 0.f);
            G[(size_t)(o + r) * FN + o + i] = val;
        }
        __syncthreads();
        if (p < 3) {
            for (int pos = tid; pos < 32 * 32; pos += 512) {
                int i = pos >> 5, r = pos & 31;
                if (r < i) VP(o + r, i) = 0.f;
            }
            __syncthreads();
            build_T(Vp, Wm2, Tp, taus, o, tid);
            if (p == 0)      block_apply<96>(G, 0,  32, Vp, Tp, Wm, Wm2, tid);
            else if (p == 1) block_apply<64>(G, 32, 64, Vp, Tp, Wm, Wm2, tid);
            else             block_apply<32>(G, 64, 96, Vp, Tp, Wm, Wm2, tid);
        }
    }
    __syncthreads();

    // ---------------- R^{-1} with 8-column ILP per warp ----------------
    float* Rsm = sm;             // 128 x 130 (overlays Vp)
    float* rd  = sm + 16640;     // 128 reciprocals
    for (int e = tid; e < 128 * 128; e += 512) {
        int r = e >> 7, c = e & 127;
        Rsm[r * 130 + c] = G[(size_t)r * FN + c];
    }
    __syncthreads();
    if (tid < 128) rd[tid] = 1.f / Rsm[tid * 130 + tid];
    __syncthreads();

    float xr[8][4];   // warp w owns columns c = w + 16m
    #pragma unroll
    for (int m = 0; m < 8; m++) {
        #pragma unroll
        for (int q = 0; q < 4; q++) xr[m][q] = 0.f;
        int c = w + (m << 4);
        float dv = rd[c];
        if ((c & 31) == lane) {
            int q = c >> 5;
            if (q == 0) xr[m][0] = dv; else if (q == 1) xr[m][1] = dv;
            else if (q == 2) xr[m][2] = dv; else xr[m][3] = dv;
        }
    }
    for (int k = 126; k >= 0; k--) {
        const float* Rk = Rsm + k * 130;
        float r0 = Rk[lane], r1 = Rk[lane + 32], r2 = Rk[lane + 64], r3 = Rk[lane + 96];
        float rk = rd[k];
        int qk = k >> 5, lk = k & 31;
        #pragma unroll
        for (int m = 0; m < 8; m++) {
            int c = w + (m << 4);
            if (c > k) {
                float s = r0 * xr[m][0] + r1 * xr[m][1] + r2 * xr[m][2] + r3 * xr[m][3];
                s = wsum(s);
                float xk = -s * rk;
                if (lk == lane) {
                    if (qk == 0) xr[m][0] = xk; else if (qk == 1) xr[m][1] = xk;
                    else if (qk == 2) xr[m][2] = xk; else xr[m][3] = xk;
                }
            }
        }
    }
    __syncthreads();   // all solve reads of Rsm complete

    // ---------------- Rinv -> SMEM (stride-130, reads are warp-uniform) ----------------
    float* Rg = sm;              // 128 x 130 (in place of Rsm)
    float* Ys = sm + 16640;      // 128 x 66
    #pragma unroll
    for (int m = 0; m < 8; m++) {
        int c = w + (m << 4);
        float* dst = Rg + c;
        dst[(size_t)lane * RGS]        = xr[m][0];
        dst[(size_t)(lane + 32) * RGS] = xr[m][1];
        dst[(size_t)(lane + 64) * RGS] = xr[m][2];
        dst[(size_t)(lane + 96) * RGS] = xr[m][3];
    }
    __syncthreads();

    // ---------------- Q = Y * Rinv (8 tiles of 64 rows, 2 rows/thread) ----------------
    const int cA = 4 * w, cB = 124 - 4 * w;
    const int kmaxA = cA + 4, kmaxB = cB + 4;
    const float* RgA = Rg + cA;
    const float* RgB = Rg + cB;

    for (int tile = 0; tile < 8; tile++) {
        const int t0 = tile * 64;
        #pragma unroll
        for (int e = tid; e < 64 * 32; e += 512) {
            int r = e >> 5, g4 = e & 31;
            float4 v = *(const float4*)(Y + (size_t)(t0 + r) * FN + g4 * 4);
            float* dst = Ys + (g4 * 4) * 66 + r;
            dst[0] = v.x; dst[66] = v.y; dst[132] = v.z; dst[198] = v.w;
        }
        __syncthreads();

        ull aA0 = 0ull, aA1 = 0ull, aB0 = 0ull, aB1 = 0ull;   // row lane
        ull bA0 = 0ull, bA1 = 0ull, bB0 = 0ull, bB1 = 0ull;   // row lane+32
        const float* yb0 = Ys + lane;
        const float* yb1 = Ys + lane + 32;
        int k = 0;
        for (; k < kmaxA; k++) {
            float y0 = yb0[k * 66], y1 = yb1[k * 66];
            ull v0 = pk2(y0, y0), v1 = pk2(y1, y1);
            const ull* wa = (const ull*)(RgA + k * RGS);
            const ull* wb = (const ull*)(RgB + k * RGS);
            ull wa0 = wa[0], wa1 = wa[1], wb0 = wb[0], wb1 = wb[1];
            aA0 = fma2(v0, wa0, aA0); aA1 = fma2(v0, wa1, aA1);
            aB0 = fma2(v0, wb0, aB0); aB1 = fma2(v0, wb1, aB1);
            bA0 = fma2(v1, wa0, bA0); bA1 = fma2(v1, wa1, bA1);
            bB0 = fma2(v1, wb0, bB0); bB1 = fma2(v1, wb1, bB1);
        }
        for (; k < kmaxB; k++) {
            float y0 = yb0[k * 66], y1 = yb1[k * 66];
            ull v0 = pk2(y0, y0), v1 = pk2(y1, y1);
            const ull* wb = (const ull*)(RgB + k * RGS);
            ull wb0 = wb[0], wb1 = wb[1];
            aB0 = fma2(v0, wb0, aB0); aB1 = fma2(v0, wb1, aB1);
            bB0 = fma2(v1, wb0, bB0); bB1 = fma2(v1, wb1, bB1);
        }
        __syncthreads();   // done reading Ys before restage

        float* orow0 = Y + (size_t)(t0 + lane) * FN;
        float* orow1 = Y + (size_t)(t0 + lane + 32) * FN;
        ulonglong2 q;
        q.x = aA0; q.y = aA1; *(ulonglong2*)(orow0 + cA) = q;
        q.x = aB0; q.y = aB1; *(ulonglong2*)(orow0 + cB) = q;
        q.x = bA0; q.y = bA1; *(ulonglong2*)(orow1 + cA) = q;
        q.x = bB0; q.y = bB1; *(ulonglong2*)(orow1 + cB) = q;
    }
}

// ============================================================
extern "C" void kernel_launch(void* const* d_in, const int* in_sizes, int n_in,
                              void* d_out, int out_size)
{
    const float* x    = (const float*)d_in[0];
    const float* W    = (const float*)d_in[1];
    const float* bias = (const float*)d_in[2];
    float* out = (float*)d_out;

    cudaFuncSetAttribute(qr_kernel, cudaFuncAttributeMaxDynamicSharedMemorySize, SM_BYTES);

    dim3 cgrid(TN / 64, BN);
    conv_kernel<<<cgrid, 256>>>(x, W, bias, out);   // Y -> d_out AND scratch
    qr_kernel<<<BN, 512, SM_BYTES>>>(out);          // geqrf + Rinv + Q, in-place
}

// round 15
// speedup vs baseline: 1.2334x; 1.1035x over previous
#include <cuda_runtime.h>

#define BN 256
#define TN 512
#define CN 128
#define FN 128
#define NB 32
#define VS 34      /* Vp row stride (even -> 8B-aligned col pairs) */

typedef unsigned long long ull;

__device__ float g_scratch[(size_t)BN * TN * FN];   // 64 MB scratch

__device__ __forceinline__ ull pk2(float lo, float hi) {
    ull r; asm("mov.b64 %0, {%1, %2};" : "=l"(r) : "f"(lo), "f"(hi)); return r;
}
__device__ __forceinline__ void upk2(ull v, float& lo, float& hi) {
    asm("mov.b64 {%0, %1}, %2;" : "=f"(lo), "=f"(hi) : "l"(v));
}
__device__ __forceinline__ ull fma2(ull a, ull b, ull c) {
    ull d; asm("fma.rn.f32x2 %0, %1, %2, %3;" : "=l"(d) : "l"(a), "l"(b), "l"(c)); return d;
}
__device__ __forceinline__ float wsum(float v) {
    #pragma unroll
    for (int o = 16; o; o >>= 1) v += __shfl_xor_sync(0xffffffffu, v, o);
    return v;
}

// ============================================================
// Conv1D (256 threads, 8 rows x 4 cols/thread — proven fastest variant).
// Writes y to BOTH d_out (preserved Y) and scratch (working copy).
// ============================================================
__global__ __launch_bounds__(256) void conv_kernel(
    const float* __restrict__ x, const float* __restrict__ W,
    const float* __restrict__ bias, float* __restrict__ y)
{
    __shared__ float Xs[64][33];
    __shared__ float Ws[32][128];

    const int b = blockIdx.y, t0 = blockIdx.x * 64, tid = threadIdx.x;
    const int lane = tid & 31, warp = tid >> 5;
    const int cbase = lane * 4, rbase = warp * 8;

    ull acc2[8][2];
    #pragma unroll
    for (int i = 0; i < 8; i++) { acc2[i][0] = 0ull; acc2[i][1] = 0ull; }

    for (int k = 0; k < 3; k++) {
        for (int c0 = 0; c0 < CN; c0 += 32) {
            #pragma unroll
            for (int q = 0; q < 16; q++) {
                int e = tid + 256 * q, f = e & 127, cc = e >> 7;
                Ws[cc][f] = W[((size_t)(k * CN + c0 + cc)) * FN + f];
            }
            #pragma unroll
            for (int q = 0; q < 8; q++) {
                int e = tid + 256 * q, cc = e & 31, r = e >> 5;
                int t = t0 + r + k - 1;
                float v = 0.f;
                if (t >= 0 && t < TN) v = x[((size_t)b * TN + t) * CN + c0 + cc];
                Xs[r][cc] = v;
            }
            __syncthreads();
            #pragma unroll
            for (int cc = 0; cc < 32; cc++) {
                const ull* wp = (const ull*)&Ws[cc][cbase];
                ull w01 = wp[0], w23 = wp[1];
                #pragma unroll
                for (int i = 0; i < 8; i++) {
                    float xv = Xs[rbase + i][cc];
                    ull xx = pk2(xv, xv);
                    acc2[i][0] = fma2(xx, w01, acc2[i][0]);
                    acc2[i][1] = fma2(xx, w23, acc2[i][1]);
                }
            }
            __syncthreads();
        }
    }
    float b0 = bias[cbase], b1 = bias[cbase+1], b2 = bias[cbase+2], b3 = bias[cbase+3];
    #pragma unroll
    for (int i = 0; i < 8; i++) {
        int t = t0 + rbase + i;
        float4 o; float lo, hi;
        upk2(acc2[i][0], lo, hi); o.x = lo + b0; o.y = hi + b1;
        upk2(acc2[i][1], lo, hi); o.z = lo + b2; o.w = hi + b3;
        size_t off = ((size_t)b * TN + t) * FN + cbase;
        *(float4*)&y[off] = o;
        *(float4*)&g_scratch[off] = o;
    }
}

// ============================================================
// Fused geqrf + R^{-1} + (Q = Y * Rinv), one CTA per 512x128 matrix.
// ============================================================
#define VP(t,i)   Vp[(t) * VS + (i)]
#define W2STRIDE  120
#define RGS       130   /* Rinv SMEM row stride (phase 3) */

template<int WT>
__device__ void block_apply(float* __restrict__ G, int o, int colbase,
                            const float* __restrict__ Vp, const float* __restrict__ Tp,
                            float* __restrict__ Wm, float* __restrict__ Wm2, int tid)
{
    const int lane = tid & 31, w = tid >> 5;
    constexpr int NU = WT / 32;
    constexpr int HW = WT / 2;
    constexpr int TU = 32 * HW;
    ull* Gs = (ull*)Wm2;

    // GEMM1: Wm[i][c] = sum_t V[t][i]*G[t][colbase+c]
    ull acc[NU];
    #pragma unroll
    for (int k = 0; k < NU; k++) acc[k] = 0ull;
    const int ntiles = (TN - o) >> 5;
    for (int tile = 0; tile < ntiles; tile++) {
        const int t0 = o + (tile << 5);
        #pragma unroll
        for (int u = tid; u < TU; u += 512) {
            int r = u / HW, c = u - r * HW;
            Gs[u] = *(const ull*)(G + (size_t)(t0 + r) * FN + colbase + 2 * c);
        }
        __syncthreads();
        #pragma unroll
        for (int r = 0; r < 32; r++) {
            float v = VP(t0 + r, lane);
            ull vv = pk2(v, v);
            const ull* g = Gs + r * HW + w * NU;
            #pragma unroll
            for (int k = 0; k < NU; k++) acc[k] = fma2(vv, g[k], acc[k]);
        }
        __syncthreads();
    }
    {
        ull* wout = (ull*)(Wm + lane * 96) + w * NU;
        #pragma unroll
        for (int k = 0; k < NU; k++) wout[k] = acc[k];
    }
    __syncthreads();

    // Tapply: Wm2 = -(T^T * Wm), group-10 padded
    {
        constexpr int NCG = WT / 8;
        for (int pos = tid; pos < 32 * NCG * 4; pos += 512) {
            int i = pos / (NCG * 4);
            int rem = pos - i * (NCG * 4);
            int cg = rem >> 2, k = rem & 3;
            int c = cg * 8 + 2 * k;
            ull a = 0ull;
            #pragma unroll
            for (int j = 0; j < 32; j++) {
                float tv = Tp[j * 33 + i];
                a = fma2(pk2(-tv, -tv), *(const ull*)(Wm + j * 96 + c), a);
            }
            *(ull*)(Wm2 + i * W2STRIDE + cg * 10 + 2 * k) = a;
        }
    }
    __syncthreads();

    // GEMM2: G += V * Wm2
    {
        constexpr int NCG = WT / 8;
        const int npos = ((TN - o) >> 2) * NCG;
        for (int pos = tid; pos < npos; pos += 512) {
            int tg = pos / NCG, cg = pos - tg * NCG;
            int t0 = o + (tg << 2);
            float* gp = G + (size_t)t0 * FN + colbase + cg * 8;
            ull a[4][4];
            #pragma unroll
            for (int r = 0; r < 4; r++) {
                ulonglong2 q0 = ((const ulonglong2*)(gp + r * FN))[0];
                ulonglong2 q1 = ((const ulonglong2*)(gp + r * FN))[1];
                a[r][0] = q0.x; a[r][1] = q0.y; a[r][2] = q1.x; a[r][3] = q1.y;
            }
            const float* vr0 = Vp + (size_t)t0 * VS;
            const float* vr1 = vr0 + VS;
            const float* vr2 = vr1 + VS;
            const float* vr3 = vr2 + VS;
            const float* w2base = Wm2 + cg * 10;
            #pragma unroll 4
            for (int i = 0; i < 32; i++) {
                const ull* wp = (const ull*)(w2base + i * W2STRIDE);
                ull w0 = wp[0], w1 = wp[1], w2 = wp[2], w3 = wp[3];
                float v0 = vr0[i], v1 = vr1[i], v2 = vr2[i], v3 = vr3[i];
                ull vv0 = pk2(v0, v0), vv1 = pk2(v1, v1);
                ull vv2 = pk2(v2, v2), vv3 = pk2(v3, v3);
                a[0][0] = fma2(vv0, w0, a[0][0]); a[0][1] = fma2(vv0, w1, a[0][1]);
                a[0][2] = fma2(vv0, w2, a[0][2]); a[0][3] = fma2(vv0, w3, a[0][3]);
                a[1][0] = fma2(vv1, w0, a[1][0]); a[1][1] = fma2(vv1, w1, a[1][1]);
                a[1][2] = fma2(vv1, w2, a[1][2]); a[1][3] = fma2(vv1, w3, a[1][3]);
                a[2][0] = fma2(vv2, w0, a[2][0]); a[2][1] = fma2(vv2, w1, a[2][1]);
                a[2][2] = fma2(vv2, w2, a[2][2]); a[2][3] = fma2(vv2, w3, a[2][3]);
                a[3][0] = fma2(vv3, w0, a[3][0]); a[3][1] = fma2(vv3, w1, a[3][1]);
                a[3][2] = fma2(vv3, w2, a[3][2]); a[3][3] = fma2(vv3, w3, a[3][3]);
            }
            #pragma unroll
            for (int r = 0; r < 4; r++) {
                ulonglong2 q0, q1;
                q0.x = a[r][0]; q0.y = a[r][1]; q1.x = a[r][2]; q1.y = a[r][3];
                ((ulonglong2*)(gp + r * FN))[0] = q0;
                ((ulonglong2*)(gp + r * FN))[1] = q1;
            }
        }
    }
    __syncthreads();
}

// Panel factorization: live-trimmed packed phase-A dots, row-per-thread phase C.
__device__ void panel_factor(float* Vp, float* taus, float* betas,
                             float* wred, float* rowp, float* ncoefs,
                             int o, int tid)
{
    const int lane = tid & 31, w = tid >> 5;

    for (int i = 0; i < NB; i++) {
        const int prow = o + i;
        if (w == 0) rowp[lane] = VP(prow, lane);
        // ---- Phase A: packed dots for LIVE columns only (j >= i&~1) ----
        const int pi = ((i & ~1) >> 1) + w;   // pair index this warp handles
        if (pi < 16) {
            const int ca = 2 * pi;
            ull acc = 0ull;
            #pragma unroll 2
            for (int t = prow + lane; t < TN; t += 32) {
                float vi = VP(t, i);
                ull pr = *(const ull*)&VP(t, ca);
                acc = fma2(pk2(vi, vi), pr, acc);
            }
            float p0, p1; upk2(acc, p0, p1);
            p0 = wsum(p0); p1 = wsum(p1);
            if (lane == 0) { wred[ca] = p0; wred[ca + 1] = p1; }
        }
        __syncthreads();
        // redundant scalar compute (all threads)
        float alpha = rowp[i];
        float s2 = wred[i];
        float xn2 = s2 - alpha * alpha;
        float tau, sc, beta;
        if (xn2 <= 0.f) { tau = 0.f; sc = 0.f; beta = alpha; }
        else {
            beta = -copysignf(sqrtf(s2), alpha);
            tau  = (beta - alpha) / beta;
            sc   = 1.f / (alpha - beta);
        }
        if (tid == 0) { taus[i] = tau; betas[i] = beta; }
        // warp 0: publish negated coefs + write row prow (lanes >= i only)
        if (w == 0) {
            float cjp  = rowp[lane];
            float coef = tau * (cjp + (wred[lane] - alpha * cjp) * sc);
            ncoefs[lane] = -coef;
            float nv = (lane == i) ? 1.f : cjp - coef;
            if (lane >= i) VP(prow, lane) = nv;
        }
        __syncthreads();   // coefs ready
        // ---- Phase C: one row per thread, live columns only ----
        int t = prow + 1 + tid;
        if (t < TN) {
            float* vr = Vp + (size_t)t * VS;
            float xt = vr[i];
            float vt = xt * sc;
            vr[i] = vt;
            int j = i + 1;
            if (j < NB) {
                if (j & 1) { vr[j] = fmaf(ncoefs[j], vt, vr[j]); j++; }
                ull vt2 = pk2(vt, vt);
                for (; j < NB; j += 2) {
                    ull nc  = *(const ull*)&ncoefs[j];
                    ull cur = *(const ull*)&vr[j];
                    *(ull*)&vr[j] = fma2(vt2, nc, cur);
                }
            }
        }
        __syncthreads();
    }
}

__device__ void build_T(const float* Vp, float* B, float* Tp, const float* taus,
                        int o, int tid)
{
    const int lane = tid & 31, w = tid >> 5;
    for (int i = 1; i < NB; i++) {
        for (int j = w; j < i; j += 16) {
            float p = 0.f;
            for (int t = o + i + lane; t < TN; t += 32)
                p += VP(t, j) * VP(t, i);
            p = wsum(p);
            if (lane == 0) B[j * 32 + i] = p;
        }
    }
    __syncthreads();
    if (w == 0) {
        for (int i = 0; i < NB; i++) {
            float ti = taus[i];
            float a = 0.f;
            for (int k = 0; k < i; k++)
                a += Tp[lane * 33 + k] * B[k * 32 + i];
            float tv = (lane < i) ? -ti * a : (lane == i ? ti : 0.f);
            Tp[lane * 33 + i] = tv;
            __syncwarp();
        }
    }
    __syncthreads();
}

// SMEM (floats): Vp 17408 | Tp 1056 | Wm 3072 | Wm2 3840 | taus 32 | betas 32 | wred 32 | rowp 32 | ncoefs 32 = 25536
// Phase 2 overlay: Rsm 128x130 (16640) | rd 128
// Phase 3 overlay: Rg 128x130 (16640)  | Ys 128x66 (8448) -> 25088
#define SM_FLOATS 25536
#define SM_BYTES  (SM_FLOATS * 4)

__global__ __launch_bounds__(512, 2) void qr_kernel(float* __restrict__ Yq)
{
    extern __shared__ float sm[];
    float* Vp     = sm;                 // 17408
    float* Tp     = Vp + 17408;         // 1056
    float* Wm     = Tp + 1056;          // 3072
    float* Wm2    = Wm + 3072;          // 3840 (also GEMM1 staging + build_T B)
    float* taus   = Wm2 + 3840;         // 32
    float* betas  = taus + 32;          // 32
    float* wred   = betas + 32;         // 32
    float* rowp   = wred + 32;          // 32
    float* ncoefs = rowp + 32;          // 32

    const int b = blockIdx.x;
    float* G = g_scratch + (size_t)b * TN * FN;
    float* Y = Yq + (size_t)b * TN * FN;
    const int tid = threadIdx.x;
    const int lane = tid & 31, w = tid >> 5;

    // ---------------- geqrf (blocked, trailing only) ----------------
    for (int p = 0; p < 4; p++) {
        const int o = p * 32;
        for (int t = o + w; t < TN; t += 16)
            VP(t, lane) = G[(size_t)t * FN + o + lane];
        __syncthreads();
        panel_factor(Vp, taus, betas, wred, rowp, ncoefs, o, tid);
        for (int pos = tid; pos < 32 * 32; pos += 512) {
            int r = pos >> 5, i = pos & 31;
            float val = (r < i) ? VP(o + r, i) : (r == i ? betas[i] : 0.f);
            G[(size_t)(o + r) * FN + o + i] = val;
        }
        __syncthreads();
        if (p < 3) {
            for (int pos = tid; pos < 32 * 32; pos += 512) {
                int i = pos >> 5, r = pos & 31;
                if (r < i) VP(o + r, i) = 0.f;
            }
            __syncthreads();
            build_T(Vp, Wm2, Tp, taus, o, tid);
            if (p == 0)      block_apply<96>(G, 0,  32, Vp, Tp, Wm, Wm2, tid);
            else if (p == 1) block_apply<64>(G, 32, 64, Vp, Tp, Wm, Wm2, tid);
            else             block_apply<32>(G, 64, 96, Vp, Tp, Wm, Wm2, tid);
        }
    }
    __syncthreads();

    // ---------------- R^{-1}: saxpy back-substitution, 8 cols ILP per warp ----------------
    float* Rsm = sm;             // 128 x 130 (overlays Vp)
    float* rd  = sm + 16640;     // 128 reciprocals
    for (int e = tid; e < 128 * 128; e += 512) {
        int r = e >> 7, c = e & 127;
        Rsm[r * 130 + c] = G[(size_t)r * FN + c];
    }
    __syncthreads();
    if (tid < 128) rd[tid] = 1.f / Rsm[tid * 130 + tid];
    __syncthreads();

    // xr[m][q]: column c = w + 16m, row lane + 32q.
    // Sweep k = 127..0: finalize x_k from accumulated acc_k, broadcast, saxpy rows < k.
    float xr[8][4];
    #pragma unroll
    for (int m = 0; m < 8; m++)
        #pragma unroll
        for (int q = 0; q < 4; q++) xr[m][q] = 0.f;

    #pragma unroll
    for (int q = 3; q >= 0; q--) {
        for (int kk = 31; kk >= 0; kk--) {
            const int k = q * 32 + kk;
            const float rk = rd[k];
            float rc[4];
            #pragma unroll
            for (int qq = 0; qq <= q; qq++)
                rc[qq] = Rsm[(lane + 32 * qq) * 130 + k];
            #pragma unroll
            for (int m = 0; m < 8; m++) {
                const int c = w + (m << 4);
                if (c >= k) {   // warp-uniform
                    float tmp = (k == c) ? rk : -rk * xr[m][q];
                    float xk = __shfl_sync(0xffffffffu, tmp, kk);
                    if (lane == kk) xr[m][q] = xk;
                    #pragma unroll
                    for (int qq = 0; qq < q; qq++)
                        xr[m][qq] = fmaf(rc[qq], xk, xr[m][qq]);
                    if (lane < kk) xr[m][q] = fmaf(rc[q], xk, xr[m][q]);
                }
            }
        }
    }
    __syncthreads();   // all solve reads of Rsm complete

    // ---------------- Rinv -> SMEM (stride-130, reads are warp-uniform) ----------------
    float* Rg = sm;              // 128 x 130 (in place of Rsm)
    float* Ys = sm + 16640;      // 128 x 66
    #pragma unroll
    for (int m = 0; m < 8; m++) {
        int c = w + (m << 4);
        float* dst = Rg + c;
        dst[(size_t)lane * RGS]        = xr[m][0];
        dst[(size_t)(lane + 32) * RGS] = xr[m][1];
        dst[(size_t)(lane + 64) * RGS] = xr[m][2];
        dst[(size_t)(lane + 96) * RGS] = xr[m][3];
    }
    __syncthreads();

    // ---------------- Q = Y * Rinv (8 tiles of 64 rows, 2 rows/thread) ----------------
    const int cA = 4 * w, cB = 124 - 4 * w;
    const int kmaxA = cA + 4, kmaxB = cB + 4;
    const float* RgA = Rg + cA;
    const float* RgB = Rg + cB;

    for (int tile = 0; tile < 8; tile++) {
        const int t0 = tile * 64;
        #pragma unroll
        for (int e = tid; e < 64 * 32; e += 512) {
            int r = e >> 5, g4 = e & 31;
            float4 v = *(const float4*)(Y + (size_t)(t0 + r) * FN + g4 * 4);
            float* dst = Ys + (g4 * 4) * 66 + r;
            dst[0] = v.x; dst[66] = v.y; dst[132] = v.z; dst[198] = v.w;
        }
        __syncthreads();

        ull aA0 = 0ull, aA1 = 0ull, aB0 = 0ull, aB1 = 0ull;   // row lane
        ull bA0 = 0ull, bA1 = 0ull, bB0 = 0ull, bB1 = 0ull;   // row lane+32
        const float* yb0 = Ys + lane;
        const float* yb1 = Ys + lane + 32;
        int k = 0;
        for (; k < kmaxA; k++) {
            float y0 = yb0[k * 66], y1 = yb1[k * 66];
            ull v0 = pk2(y0, y0), v1 = pk2(y1, y1);
            const ull* wa = (const ull*)(RgA + k * RGS);
            const ull* wb = (const ull*)(RgB + k * RGS);
            ull wa0 = wa[0], wa1 = wa[1], wb0 = wb[0], wb1 = wb[1];
            aA0 = fma2(v0, wa0, aA0); aA1 = fma2(v0, wa1, aA1);
            aB0 = fma2(v0, wb0, aB0); aB1 = fma2(v0, wb1, aB1);
            bA0 = fma2(v1, wa0, bA0); bA1 = fma2(v1, wa1, bA1);
            bB0 = fma2(v1, wb0, bB0); bB1 = fma2(v1, wb1, bB1);
        }
        for (; k < kmaxB; k++) {
            float y0 = yb0[k * 66], y1 = yb1[k * 66];
            ull v0 = pk2(y0, y0), v1 = pk2(y1, y1);
            const ull* wb = (const ull*)(RgB + k * RGS);
            ull wb0 = wb[0], wb1 = wb[1];
            aB0 = fma2(v0, wb0, aB0); aB1 = fma2(v0, wb1, aB1);
            bB0 = fma2(v1, wb0, bB0); bB1 = fma2(v1, wb1, bB1);
        }
        __syncthreads();   // done reading Ys before restage

        float* orow0 = Y + (size_t)(t0 + lane) * FN;
        float* orow1 = Y + (size_t)(t0 + lane + 32) * FN;
        ulonglong2 q;
        q.x = aA0; q.y = aA1; *(ulonglong2*)(orow0 + cA) = q;
        q.x = aB0; q.y = aB1; *(ulonglong2*)(orow0 + cB) = q;
        q.x = bA0; q.y = bA1; *(ulonglong2*)(orow1 + cA) = q;
        q.x = bB0; q.y = bB1; *(ulonglong2*)(orow1 + cB) = q;
    }
}

// ============================================================
extern "C" void kernel_launch(void* const* d_in, const int* in_sizes, int n_in,
                              void* d_out, int out_size)
{
    const float* x    = (const float*)d_in[0];
    const float* W    = (const float*)d_in[1];
    const float* bias = (const float*)d_in[2];
    float* out = (float*)d_out;

    cudaFuncSetAttribute(qr_kernel, cudaFuncAttributeMaxDynamicSharedMemorySize, SM_BYTES);

    dim3 cgrid(TN / 64, BN);
    conv_kernel<<<cgrid, 256>>>(x, W, bias, out);   // Y -> d_out AND scratch
    qr_kernel<<<BN, 512, SM_BYTES>>>(out);          // geqrf + Rinv + Q, in-place
}

// round 16
// speedup vs baseline: 1.2431x; 1.0079x over previous
#include <cuda_runtime.h>

#define BN 256
#define TN 512
#define CN 128
#define FN 128
#define NB 32
#define VS 34      /* Vp row stride (even -> 8B-aligned col pairs) */

typedef unsigned long long ull;

__device__ float g_scratch[(size_t)BN * TN * FN];   // 64 MB scratch

__device__ __forceinline__ ull pk2(float lo, float hi) {
    ull r; asm("mov.b64 %0, {%1, %2};" : "=l"(r) : "f"(lo), "f"(hi)); return r;
}
__device__ __forceinline__ void upk2(ull v, float& lo, float& hi) {
    asm("mov.b64 {%0, %1}, %2;" : "=f"(lo), "=f"(hi) : "l"(v));
}
__device__ __forceinline__ ull fma2(ull a, ull b, ull c) {
    ull d; asm("fma.rn.f32x2 %0, %1, %2, %3;" : "=l"(d) : "l"(a), "l"(b), "l"(c)); return d;
}
__device__ __forceinline__ float wsum(float v) {
    #pragma unroll
    for (int o = 16; o; o >>= 1) v += __shfl_xor_sync(0xffffffffu, v, o);
    return v;
}

// ============================================================
// Conv1D (256 threads, 8 rows x 4 cols/thread). Writes Y to d_out ONLY.
// ============================================================
__global__ __launch_bounds__(256) void conv_kernel(
    const float* __restrict__ x, const float* __restrict__ W,
    const float* __restrict__ bias, float* __restrict__ y)
{
    __shared__ float Xs[64][33];
    __shared__ float Ws[32][128];

    const int b = blockIdx.y, t0 = blockIdx.x * 64, tid = threadIdx.x;
    const int lane = tid & 31, warp = tid >> 5;
    const int cbase = lane * 4, rbase = warp * 8;

    ull acc2[8][2];
    #pragma unroll
    for (int i = 0; i < 8; i++) { acc2[i][0] = 0ull; acc2[i][1] = 0ull; }

    for (int k = 0; k < 3; k++) {
        for (int c0 = 0; c0 < CN; c0 += 32) {
            #pragma unroll
            for (int q = 0; q < 16; q++) {
                int e = tid + 256 * q, f = e & 127, cc = e >> 7;
                Ws[cc][f] = W[((size_t)(k * CN + c0 + cc)) * FN + f];
            }
            #pragma unroll
            for (int q = 0; q < 8; q++) {
                int e = tid + 256 * q, cc = e & 31, r = e >> 5;
                int t = t0 + r + k - 1;
                float v = 0.f;
                if (t >= 0 && t < TN) v = x[((size_t)b * TN + t) * CN + c0 + cc];
                Xs[r][cc] = v;
            }
            __syncthreads();
            #pragma unroll
            for (int cc = 0; cc < 32; cc++) {
                const ull* wp = (const ull*)&Ws[cc][cbase];
                ull w01 = wp[0], w23 = wp[1];
                #pragma unroll
                for (int i = 0; i < 8; i++) {
                    float xv = Xs[rbase + i][cc];
                    ull xx = pk2(xv, xv);
                    acc2[i][0] = fma2(xx, w01, acc2[i][0]);
                    acc2[i][1] = fma2(xx, w23, acc2[i][1]);
                }
            }
            __syncthreads();
        }
    }
    float b0 = bias[cbase], b1 = bias[cbase+1], b2 = bias[cbase+2], b3 = bias[cbase+3];
    #pragma unroll
    for (int i = 0; i < 8; i++) {
        int t = t0 + rbase + i;
        float4 o; float lo, hi;
        upk2(acc2[i][0], lo, hi); o.x = lo + b0; o.y = hi + b1;
        upk2(acc2[i][1], lo, hi); o.z = lo + b2; o.w = hi + b3;
        *(float4*)&y[((size_t)b * TN + t) * FN + cbase] = o;
    }
}

// ============================================================
// Fused geqrf + R^{-1} + (Q = Y * Rinv), one CTA per 512x128 matrix.
// p=0 reads from pristine Y, writes updates to scratch G; p>=1 G->G.
// ============================================================
#define VP(t,i)   Vp[(t) * VS + (i)]
#define W2STRIDE  120
#define RGS       132   /* Rinv SMEM row stride (phase 3; 16B-aligned rows) */

template<int WT>
__device__ void block_apply(const float* __restrict__ Gin, float* __restrict__ Gout,
                            int o, int colbase,
                            const float* __restrict__ Vp, const float* __restrict__ Tp,
                            float* __restrict__ Wm, float* __restrict__ Wm2, int tid)
{
    const int lane = tid & 31, w = tid >> 5;
    constexpr int NU = WT / 32;
    constexpr int HW = WT / 2;
    constexpr int TU = 32 * HW;
    ull* Gs = (ull*)Wm2;

    // GEMM1: Wm[i][c] = sum_t V[t][i]*Gin[t][colbase+c]
    ull acc[NU];
    #pragma unroll
    for (int k = 0; k < NU; k++) acc[k] = 0ull;
    const int ntiles = (TN - o) >> 5;
    for (int tile = 0; tile < ntiles; tile++) {
        const int t0 = o + (tile << 5);
        #pragma unroll
        for (int u = tid; u < TU; u += 512) {
            int r = u / HW, c = u - r * HW;
            Gs[u] = *(const ull*)(Gin + (size_t)(t0 + r) * FN + colbase + 2 * c);
        }
        __syncthreads();
        #pragma unroll
        for (int r = 0; r < 32; r++) {
            float v = VP(t0 + r, lane);
            ull vv = pk2(v, v);
            const ull* g = Gs + r * HW + w * NU;
            #pragma unroll
            for (int k = 0; k < NU; k++) acc[k] = fma2(vv, g[k], acc[k]);
        }
        __syncthreads();
    }
    {
        ull* wout = (ull*)(Wm + lane * 96) + w * NU;
        #pragma unroll
        for (int k = 0; k < NU; k++) wout[k] = acc[k];
    }
    __syncthreads();

    // Tapply: Wm2 = -(T^T * Wm), group-10 padded
    {
        constexpr int NCG = WT / 8;
        for (int pos = tid; pos < 32 * NCG * 4; pos += 512) {
            int i = pos / (NCG * 4);
            int rem = pos - i * (NCG * 4);
            int cg = rem >> 2, k = rem & 3;
            int c = cg * 8 + 2 * k;
            ull a = 0ull;
            #pragma unroll
            for (int j = 0; j < 32; j++) {
                float tv = Tp[j * 33 + i];
                a = fma2(pk2(-tv, -tv), *(const ull*)(Wm + j * 96 + c), a);
            }
            *(ull*)(Wm2 + i * W2STRIDE + cg * 10 + 2 * k) = a;
        }
    }
    __syncthreads();

    // GEMM2: Gout = Gin + V * Wm2
    {
        constexpr int NCG = WT / 8;
        const int npos = ((TN - o) >> 2) * NCG;
        for (int pos = tid; pos < npos; pos += 512) {
            int tg = pos / NCG, cg = pos - tg * NCG;
            int t0 = o + (tg << 2);
            const float* gpi = Gin  + (size_t)t0 * FN + colbase + cg * 8;
            float*       gpo = Gout + (size_t)t0 * FN + colbase + cg * 8;
            ull a[4][4];
            #pragma unroll
            for (int r = 0; r < 4; r++) {
                ulonglong2 q0 = ((const ulonglong2*)(gpi + r * FN))[0];
                ulonglong2 q1 = ((const ulonglong2*)(gpi + r * FN))[1];
                a[r][0] = q0.x; a[r][1] = q0.y; a[r][2] = q1.x; a[r][3] = q1.y;
            }
            const float* vr0 = Vp + (size_t)t0 * VS;
            const float* vr1 = vr0 + VS;
            const float* vr2 = vr1 + VS;
            const float* vr3 = vr2 + VS;
            const float* w2base = Wm2 + cg * 10;
            #pragma unroll 4
            for (int i = 0; i < 32; i++) {
                const ull* wp = (const ull*)(w2base + i * W2STRIDE);
                ull w0 = wp[0], w1 = wp[1], w2 = wp[2], w3 = wp[3];
                float v0 = vr0[i], v1 = vr1[i], v2 = vr2[i], v3 = vr3[i];
                ull vv0 = pk2(v0, v0), vv1 = pk2(v1, v1);
                ull vv2 = pk2(v2, v2), vv3 = pk2(v3, v3);
                a[0][0] = fma2(vv0, w0, a[0][0]); a[0][1] = fma2(vv0, w1, a[0][1]);
                a[0][2] = fma2(vv0, w2, a[0][2]); a[0][3] = fma2(vv0, w3, a[0][3]);
                a[1][0] = fma2(vv1, w0, a[1][0]); a[1][1] = fma2(vv1, w1, a[1][1]);
                a[1][2] = fma2(vv1, w2, a[1][2]); a[1][3] = fma2(vv1, w3, a[1][3]);
                a[2][0] = fma2(vv2, w0, a[2][0]); a[2][1] = fma2(vv2, w1, a[2][1]);
                a[2][2] = fma2(vv2, w2, a[2][2]); a[2][3] = fma2(vv2, w3, a[2][3]);
                a[3][0] = fma2(vv3, w0, a[3][0]); a[3][1] = fma2(vv3, w1, a[3][1]);
                a[3][2] = fma2(vv3, w2, a[3][2]); a[3][3] = fma2(vv3, w3, a[3][3]);
            }
            #pragma unroll
            for (int r = 0; r < 4; r++) {
                ulonglong2 q0, q1;
                q0.x = a[r][0]; q0.y = a[r][1]; q1.x = a[r][2]; q1.y = a[r][3];
                ((ulonglong2*)(gpo + r * FN))[0] = q0;
                ((ulonglong2*)(gpo + r * FN))[1] = q1;
            }
        }
    }
    __syncthreads();
}

// Panel factorization: live-trimmed packed phase-A dots, row-per-thread phase C.
__device__ void panel_factor(float* Vp, float* taus, float* betas,
                             float* wred, float* rowp, float* ncoefs,
                             int o, int tid)
{
    const int lane = tid & 31, w = tid >> 5;

    for (int i = 0; i < NB; i++) {
        const int prow = o + i;
        if (w == 0) rowp[lane] = VP(prow, lane);
        // ---- Phase A: packed dots for LIVE columns only ----
        const int pi = ((i & ~1) >> 1) + w;
        if (pi < 16) {
            const int ca = 2 * pi;
            ull acc = 0ull;
            #pragma unroll 2
            for (int t = prow + lane; t < TN; t += 32) {
                float vi = VP(t, i);
                ull pr = *(const ull*)&VP(t, ca);
                acc = fma2(pk2(vi, vi), pr, acc);
            }
            float p0, p1; upk2(acc, p0, p1);
            p0 = wsum(p0); p1 = wsum(p1);
            if (lane == 0) { wred[ca] = p0; wred[ca + 1] = p1; }
        }
        __syncthreads();
        float alpha = rowp[i];
        float s2 = wred[i];
        float xn2 = s2 - alpha * alpha;
        float tau, sc, beta;
        if (xn2 <= 0.f) { tau = 0.f; sc = 0.f; beta = alpha; }
        else {
            beta = -copysignf(sqrtf(s2), alpha);
            tau  = (beta - alpha) / beta;
            sc   = 1.f / (alpha - beta);
        }
        if (tid == 0) { taus[i] = tau; betas[i] = beta; }
        if (w == 0) {
            float cjp  = rowp[lane];
            float coef = tau * (cjp + (wred[lane] - alpha * cjp) * sc);
            ncoefs[lane] = -coef;
            float nv = (lane == i) ? 1.f : cjp - coef;
            if (lane >= i) VP(prow, lane) = nv;
        }
        __syncthreads();
        // ---- Phase C: one row per thread, live columns only ----
        int t = prow + 1 + tid;
        if (t < TN) {
            float* vr = Vp + (size_t)t * VS;
            float xt = vr[i];
            float vt = xt * sc;
            vr[i] = vt;
            int j = i + 1;
            if (j < NB) {
                if (j & 1) { vr[j] = fmaf(ncoefs[j], vt, vr[j]); j++; }
                ull vt2 = pk2(vt, vt);
                for (; j < NB; j += 2) {
                    ull nc  = *(const ull*)&ncoefs[j];
                    ull cur = *(const ull*)&vr[j];
                    *(ull*)&vr[j] = fma2(vt2, nc, cur);
                }
            }
        }
        __syncthreads();
    }
}

__device__ void build_T(const float* Vp, float* B, float* Tp, const float* taus,
                        int o, int tid)
{
    const int lane = tid & 31, w = tid >> 5;
    for (int i = 1; i < NB; i++) {
        for (int j = w; j < i; j += 16) {
            float p = 0.f;
            for (int t = o + i + lane; t < TN; t += 32)
                p += VP(t, j) * VP(t, i);
            p = wsum(p);
            if (lane == 0) B[j * 32 + i] = p;
        }
    }
    __syncthreads();
    if (w == 0) {
        for (int i = 0; i < NB; i++) {
            float ti = taus[i];
            float a = 0.f;
            for (int k = 0; k < i; k++)
                a += Tp[lane * 33 + k] * B[k * 32 + i];
            float tv = (lane < i) ? -ti * a : (lane == i ? ti : 0.f);
            Tp[lane * 33 + i] = tv;
            __syncwarp();
        }
    }
    __syncthreads();
}

// SMEM (floats): Vp 17408 | Tp 1056 | Wm 3072 | Wm2 3840 | taus 32 | betas 32 | wred 32 | rowp 32 | ncoefs 32 = 25536
// Phase 2 overlay: Rsm 128x130 (16640) | rd 128
// Phase 3 overlay: Rg 128x132 (16896)  | Ys 128x66 (8448) -> 25344
#define SM_FLOATS 25536
#define SM_BYTES  (SM_FLOATS * 4)

__global__ __launch_bounds__(512, 2) void qr_kernel(float* __restrict__ Yq)
{
    extern __shared__ float sm[];
    float* Vp     = sm;                 // 17408
    float* Tp     = Vp + 17408;         // 1056
    float* Wm     = Tp + 1056;          // 3072
    float* Wm2    = Wm + 3072;          // 3840 (also GEMM1 staging + build_T B)
    float* taus   = Wm2 + 3840;         // 32
    float* betas  = taus + 32;          // 32
    float* wred   = betas + 32;         // 32
    float* rowp   = wred + 32;          // 32
    float* ncoefs = rowp + 32;          // 32

    const int b = blockIdx.x;
    float* G = g_scratch + (size_t)b * TN * FN;
    float* Y = Yq + (size_t)b * TN * FN;
    const int tid = threadIdx.x;
    const int lane = tid & 31, w = tid >> 5;

    // ---------------- geqrf (blocked; p=0 reads Y, writes G) ----------------
    for (int p = 0; p < 4; p++) {
        const int o = p * 32;
        const float* Gsrc = (p == 0) ? Y : G;
        for (int t = o + w; t < TN; t += 16)
            VP(t, lane) = Gsrc[(size_t)t * FN + o + lane];
        __syncthreads();
        panel_factor(Vp, taus, betas, wred, rowp, ncoefs, o, tid);
        for (int pos = tid; pos < 32 * 32; pos += 512) {
            int r = pos >> 5, i = pos & 31;
            float val = (r < i) ? VP(o + r, i) : (r == i ? betas[i] : 0.f);
            G[(size_t)(o + r) * FN + o + i] = val;
        }
        __syncthreads();
        if (p < 3) {
            for (int pos = tid; pos < 32 * 32; pos += 512) {
                int i = pos >> 5, r = pos & 31;
                if (r < i) VP(o + r, i) = 0.f;
            }
            __syncthreads();
            build_T(Vp, Wm2, Tp, taus, o, tid);
            if (p == 0)      block_apply<96>(Y, G, 0,  32, Vp, Tp, Wm, Wm2, tid);
            else if (p == 1) block_apply<64>(G, G, 32, 64, Vp, Tp, Wm, Wm2, tid);
            else             block_apply<32>(G, G, 64, 96, Vp, Tp, Wm, Wm2, tid);
        }
    }
    __syncthreads();

    // ---------------- R^{-1}: saxpy back-substitution, 8 cols ILP per warp ----------------
    float* Rsm = sm;             // 128 x 130 (overlays Vp)
    float* rd  = sm + 16640;     // 128 reciprocals
    for (int e = tid; e < 128 * 128; e += 512) {
        int r = e >> 7, c = e & 127;
        Rsm[r * 130 + c] = G[(size_t)r * FN + c];
    }
    __syncthreads();
    if (tid < 128) rd[tid] = 1.f / Rsm[tid * 130 + tid];
    __syncthreads();

    float xr[8][4];   // column c = w + 16m, row lane + 32q
    #pragma unroll
    for (int m = 0; m < 8; m++)
        #pragma unroll
        for (int q = 0; q < 4; q++) xr[m][q] = 0.f;

    #pragma unroll
    for (int q = 3; q >= 0; q--) {
        for (int kk = 31; kk >= 0; kk--) {
            const int k = q * 32 + kk;
            const float rk = rd[k];
            float rc[4];
            #pragma unroll
            for (int qq = 0; qq <= q; qq++)
                rc[qq] = Rsm[(lane + 32 * qq) * 130 + k];
            #pragma unroll
            for (int m = 0; m < 8; m++) {
                const int c = w + (m << 4);
                if (c >= k) {   // warp-uniform
                    float tmp = (k == c) ? rk : -rk * xr[m][q];
                    float xk = __shfl_sync(0xffffffffu, tmp, kk);
                    if (lane == kk) xr[m][q] = xk;
                    #pragma unroll
                    for (int qq = 0; qq < q; qq++)
                        xr[m][qq] = fmaf(rc[qq], xk, xr[m][qq]);
                    if (lane < kk) xr[m][q] = fmaf(rc[q], xk, xr[m][q]);
                }
            }
        }
    }
    __syncthreads();   // all solve reads of Rsm complete

    // ---------------- Rinv -> SMEM (stride-132, 16B-aligned rows) ----------------
    float* Rg = sm;              // 128 x 132 (overlays Rsm/rd)
    float* Ys = sm + 16896;      // 128 x 66
    #pragma unroll
    for (int m = 0; m < 8; m++) {
        int c = w + (m << 4);
        float* dst = Rg + c;
        dst[(size_t)lane * RGS]        = xr[m][0];
        dst[(size_t)(lane + 32) * RGS] = xr[m][1];
        dst[(size_t)(lane + 64) * RGS] = xr[m][2];
        dst[(size_t)(lane + 96) * RGS] = xr[m][3];
    }
    __syncthreads();

    // ---------------- Q = Y * Rinv (8 tiles of 64 rows, 2 rows/thread) ----------------
    const int cA = 4 * w, cB = 124 - 4 * w;
    const int kmaxA = cA + 4, kmaxB = cB + 4;
    const float* RgA = Rg + cA;   // 16B-aligned (cA = 4w floats, row stride 132)
    const float* RgB = Rg + cB;

    for (int tile = 0; tile < 8; tile++) {
        const int t0 = tile * 64;
        #pragma unroll
        for (int e = tid; e < 64 * 32; e += 512) {
            int r = e >> 5, g4 = e & 31;
            float4 v = *(const float4*)(Y + (size_t)(t0 + r) * FN + g4 * 4);
            float* dst = Ys + (g4 * 4) * 66 + r;
            dst[0] = v.x; dst[66] = v.y; dst[132] = v.z; dst[198] = v.w;
        }
        __syncthreads();

        ull aA0 = 0ull, aA1 = 0ull, aB0 = 0ull, aB1 = 0ull;   // row lane
        ull bA0 = 0ull, bA1 = 0ull, bB0 = 0ull, bB1 = 0ull;   // row lane+32
        const float* yb0 = Ys + lane;
        const float* yb1 = Ys + lane + 32;
        int k = 0;
        for (; k < kmaxA; k++) {
            float y0 = yb0[k * 66], y1 = yb1[k * 66];
            ull v0 = pk2(y0, y0), v1 = pk2(y1, y1);
            ulonglong2 wa = *(const ulonglong2*)(RgA + k * RGS);
            ulonglong2 wb = *(const ulonglong2*)(RgB + k * RGS);
            aA0 = fma2(v0, wa.x, aA0); aA1 = fma2(v0, wa.y, aA1);
            aB0 = fma2(v0, wb.x, aB0); aB1 = fma2(v0, wb.y, aB1);
            bA0 = fma2(v1, wa.x, bA0); bA1 = fma2(v1, wa.y, bA1);
            bB0 = fma2(v1, wb.x, bB0); bB1 = fma2(v1, wb.y, bB1);
        }
        for (; k < kmaxB; k++) {
            float y0 = yb0[k * 66], y1 = yb1[k * 66];
            ull v0 = pk2(y0, y0), v1 = pk2(y1, y1);
            ulonglong2 wb = *(const ulonglong2*)(RgB + k * RGS);
            aB0 = fma2(v0, wb.x, aB0); aB1 = fma2(v0, wb.y, aB1);
            bB0 = fma2(v1, wb.x, bB0); bB1 = fma2(v1, wb.y, bB1);
        }
        __syncthreads();   // done reading Ys before restage

        float* orow0 = Y + (size_t)(t0 + lane) * FN;
        float* orow1 = Y + (size_t)(t0 + lane + 32) * FN;
        ulonglong2 q;
        q.x = aA0; q.y = aA1; *(ulonglong2*)(orow0 + cA) = q;
        q.x = aB0; q.y = aB1; *(ulonglong2*)(orow0 + cB) = q;
        q.x = bA0; q.y = bA1; *(ulonglong2*)(orow1 + cA) = q;
        q.x = bB0; q.y = bB1; *(ulonglong2*)(orow1 + cB) = q;
    }
}

// ============================================================
extern "C" void kernel_launch(void* const* d_in, const int* in_sizes, int n_in,
                              void* d_out, int out_size)
{
    const float* x    = (const float*)d_in[0];
    const float* W    = (const float*)d_in[1];
    const float* bias = (const float*)d_in[2];
    float* out = (float*)d_out;

    cudaFuncSetAttribute(qr_kernel, cudaFuncAttributeMaxDynamicSharedMemorySize, SM_BYTES);

    dim3 cgrid(TN / 64, BN);
    conv_kernel<<<cgrid, 256>>>(x, W, bias, out);   // Y -> d_out only
    qr_kernel<<<BN, 512, SM_BYTES>>>(out);          // geqrf(Y->G) + Rinv + Q, in-place
}

// round 17
// speedup vs baseline: 1.2633x; 1.0162x over previous
#include <cuda_runtime.h>

#define BN 256
#define TN 512
#define CN 128
#define FN 128
#define NB 32
#define VS 34      /* Vp row stride (even -> 8B-aligned col pairs) */

typedef unsigned long long ull;

__device__ float g_scratch[(size_t)BN * TN * FN];   // 64 MB scratch

__device__ __forceinline__ ull pk2(float lo, float hi) {
    ull r; asm("mov.b64 %0, {%1, %2};" : "=l"(r) : "f"(lo), "f"(hi)); return r;
}
__device__ __forceinline__ void upk2(ull v, float& lo, float& hi) {
    asm("mov.b64 {%0, %1}, %2;" : "=f"(lo), "=f"(hi) : "l"(v));
}
__device__ __forceinline__ ull fma2(ull a, ull b, ull c) {
    ull d; asm("fma.rn.f32x2 %0, %1, %2, %3;" : "=l"(d) : "l"(a), "l"(b), "l"(c)); return d;
}
__device__ __forceinline__ float wsum(float v) {
    #pragma unroll
    for (int o = 16; o; o >>= 1) v += __shfl_xor_sync(0xffffffffu, v, o);
    return v;
}

// ============================================================
// Conv1D: stage X once + all 3 taps per c0 chunk; shared xp packing.
// 256 threads, 8 rows x 4 cols/thread. Writes Y to d_out only.
// ============================================================
#define CONV_SM ((66 * 33 + 3 * 32 * 128) * 4)

__global__ __launch_bounds__(256, 3) void conv_kernel(
    const float* __restrict__ x, const float* __restrict__ W,
    const float* __restrict__ bias, float* __restrict__ y)
{
    extern __shared__ float csm[];
    float (*Xs)[33] = (float (*)[33])csm;          // 66 x 33
    float* Ws       = csm + 66 * 33;               // [k][cc][f] 3*32*128

    const int b = blockIdx.y, t0 = blockIdx.x * 64, tid = threadIdx.x;
    const int lane = tid & 31, warp = tid >> 5;
    const int cbase = lane * 4, rbase = warp * 8;

    ull acc2[8][2];
    #pragma unroll
    for (int i = 0; i < 8; i++) { acc2[i][0] = 0ull; acc2[i][1] = 0ull; }

    for (int c0 = 0; c0 < CN; c0 += 32) {
        // stage W: all 3 taps for this channel chunk (3*32*128 floats)
        #pragma unroll
        for (int q = 0; q < 48; q++) {
            int e = tid + 256 * q;
            int f = e & 127, rest = e >> 7;
            int cc = rest & 31, k = rest >> 5;
            Ws[e] = W[((size_t)(k * CN + c0 + cc)) * FN + f];
        }
        // stage X: rows t0-1 .. t0+64 (66 rows) x 32 channels
        #pragma unroll
        for (int q = 0; q < 9; q++) {
            int e = tid + 256 * q;
            if (e < 66 * 32) {
                int cc = e & 31, r = e >> 5;
                int t = t0 - 1 + r;
                float v = (t >= 0 && t < TN) ? x[((size_t)b * TN + t) * CN + c0 + cc] : 0.f;
                Xs[r][cc] = v;
            }
        }
        __syncthreads();
        #pragma unroll 2
        for (int cc = 0; cc < 32; cc++) {
            ull w01[3], w23[3];
            #pragma unroll
            for (int k = 0; k < 3; k++) {
                const ull* wp = (const ull*)&Ws[(k * 32 + cc) * 128 + cbase];
                w01[k] = wp[0]; w23[k] = wp[1];
            }
            ull xp[10];
            #pragma unroll
            for (int r = 0; r < 10; r++) {
                float xv = Xs[rbase + r][cc];
                xp[r] = pk2(xv, xv);
            }
            #pragma unroll
            for (int i = 0; i < 8; i++) {
                #pragma unroll
                for (int k = 0; k < 3; k++) {
                    acc2[i][0] = fma2(xp[i + k], w01[k], acc2[i][0]);
                    acc2[i][1] = fma2(xp[i + k], w23[k], acc2[i][1]);
                }
            }
        }
        __syncthreads();
    }
    float b0 = bias[cbase], b1 = bias[cbase+1], b2 = bias[cbase+2], b3 = bias[cbase+3];
    #pragma unroll
    for (int i = 0; i < 8; i++) {
        int t = t0 + rbase + i;
        float4 o; float lo, hi;
        upk2(acc2[i][0], lo, hi); o.x = lo + b0; o.y = hi + b1;
        upk2(acc2[i][1], lo, hi); o.z = lo + b2; o.w = hi + b3;
        *(float4*)&y[((size_t)b * TN + t) * FN + cbase] = o;
    }
}

// ============================================================
// Fused geqrf + R^{-1} + (Q = Y * Rinv), one CTA per 512x128 matrix.
// ============================================================
#define VP(t,i)   Vp[(t) * VS + (i)]
#define W2STRIDE  120
#define RGS       132   /* Rinv SMEM row stride (phase 3; 16B-aligned rows) */

template<int WT>
__device__ void block_apply(const float* __restrict__ Gin, float* __restrict__ Gout,
                            int o, int colbase,
                            const float* __restrict__ Vp, const float* __restrict__ Tp,
                            float* __restrict__ Wm, float* __restrict__ Wm2, int tid)
{
    const int lane = tid & 31, w = tid >> 5;
    constexpr int NU = WT / 32;
    constexpr int HW = WT / 2;
    constexpr int HB = 16 * HW;     // ull per 16-row buffer
    ull* Gs = (ull*)Wm2;            // two buffers: [0,HB) and [HB,2HB)

    // GEMM1: Wm[i][c] = sum_t V[t][i]*Gin[t][colbase+c]  (double-buffered)
    ull acc[NU];
    #pragma unroll
    for (int k = 0; k < NU; k++) acc[k] = 0ull;
    const int ntiles = (TN - o) >> 4;
    // prologue: stage tile 0
    for (int u = tid; u < HB; u += 512) {
        int r = u / HW, c = u - r * HW;
        Gs[u] = *(const ull*)(Gin + (size_t)(o + r) * FN + colbase + 2 * c);
    }
    __syncthreads();
    for (int tile = 0; tile < ntiles; tile++) {
        ull* cur = Gs + (tile & 1) * HB;
        if (tile + 1 < ntiles) {
            ull* nxt = Gs + ((tile + 1) & 1) * HB;
            const int t1 = o + ((tile + 1) << 4);
            for (int u = tid; u < HB; u += 512) {
                int r = u / HW, c = u - r * HW;
                nxt[u] = *(const ull*)(Gin + (size_t)(t1 + r) * FN + colbase + 2 * c);
            }
        }
        const int t0 = o + (tile << 4);
        #pragma unroll
        for (int r = 0; r < 16; r++) {
            float v = VP(t0 + r, lane);
            ull vv = pk2(v, v);
            const ull* g = cur + r * HW + w * NU;
            #pragma unroll
            for (int k = 0; k < NU; k++) acc[k] = fma2(vv, g[k], acc[k]);
        }
        __syncthreads();
    }
    {
        ull* wout = (ull*)(Wm + lane * 96) + w * NU;
        #pragma unroll
        for (int k = 0; k < NU; k++) wout[k] = acc[k];
    }
    __syncthreads();

    // Tapply: Wm2 = -(T^T * Wm), group-10 padded
    {
        constexpr int NCG = WT / 8;
        for (int pos = tid; pos < 32 * NCG * 4; pos += 512) {
            int i = pos / (NCG * 4);
            int rem = pos - i * (NCG * 4);
            int cg = rem >> 2, k = rem & 3;
            int c = cg * 8 + 2 * k;
            ull a = 0ull;
            #pragma unroll
            for (int j = 0; j < 32; j++) {
                float tv = Tp[j * 33 + i];
                a = fma2(pk2(-tv, -tv), *(const ull*)(Wm + j * 96 + c), a);
            }
            *(ull*)(Wm2 + i * W2STRIDE + cg * 10 + 2 * k) = a;
        }
    }
    __syncthreads();

    // GEMM2: Gout = Gin + V * Wm2
    {
        constexpr int NCG = WT / 8;
        const int npos = ((TN - o) >> 2) * NCG;
        for (int pos = tid; pos < npos; pos += 512) {
            int tg = pos / NCG, cg = pos - tg * NCG;
            int t0 = o + (tg << 2);
            const float* gpi = Gin  + (size_t)t0 * FN + colbase + cg * 8;
            float*       gpo = Gout + (size_t)t0 * FN + colbase + cg * 8;
            ull a[4][4];
            #pragma unroll
            for (int r = 0; r < 4; r++) {
                ulonglong2 q0 = ((const ulonglong2*)(gpi + r * FN))[0];
                ulonglong2 q1 = ((const ulonglong2*)(gpi + r * FN))[1];
                a[r][0] = q0.x; a[r][1] = q0.y; a[r][2] = q1.x; a[r][3] = q1.y;
            }
            const float* vr0 = Vp + (size_t)t0 * VS;
            const float* vr1 = vr0 + VS;
            const float* vr2 = vr1 + VS;
            const float* vr3 = vr2 + VS;
            const float* w2base = Wm2 + cg * 10;
            #pragma unroll 4
            for (int i = 0; i < 32; i++) {
                const ull* wp = (const ull*)(w2base + i * W2STRIDE);
                ull w0 = wp[0], w1 = wp[1], w2 = wp[2], w3 = wp[3];
                float v0 = vr0[i], v1 = vr1[i], v2 = vr2[i], v3 = vr3[i];
                ull vv0 = pk2(v0, v0), vv1 = pk2(v1, v1);
                ull vv2 = pk2(v2, v2), vv3 = pk2(v3, v3);
                a[0][0] = fma2(vv0, w0, a[0][0]); a[0][1] = fma2(vv0, w1, a[0][1]);
                a[0][2] = fma2(vv0, w2, a[0][2]); a[0][3] = fma2(vv0, w3, a[0][3]);
                a[1][0] = fma2(vv1, w0, a[1][0]); a[1][1] = fma2(vv1, w1, a[1][1]);
                a[1][2] = fma2(vv1, w2, a[1][2]); a[1][3] = fma2(vv1, w3, a[1][3]);
                a[2][0] = fma2(vv2, w0, a[2][0]); a[2][1] = fma2(vv2, w1, a[2][1]);
                a[2][2] = fma2(vv2, w2, a[2][2]); a[2][3] = fma2(vv2, w3, a[2][3]);
                a[3][0] = fma2(vv3, w0, a[3][0]); a[3][1] = fma2(vv3, w1, a[3][1]);
                a[3][2] = fma2(vv3, w2, a[3][2]); a[3][3] = fma2(vv3, w3, a[3][3]);
            }
            #pragma unroll
            for (int r = 0; r < 4; r++) {
                ulonglong2 q0, q1;
                q0.x = a[r][0]; q0.y = a[r][1]; q1.x = a[r][2]; q1.y = a[r][3];
                ((ulonglong2*)(gpo + r * FN))[0] = q0;
                ((ulonglong2*)(gpo + r * FN))[1] = q1;
            }
        }
    }
    __syncthreads();
}

// Panel factorization: live-trimmed packed phase-A dots, row-per-thread phase C.
__device__ void panel_factor(float* Vp, float* taus, float* betas,
                             float* wred, float* rowp, float* ncoefs,
                             int o, int tid)
{
    const int lane = tid & 31, w = tid >> 5;

    for (int i = 0; i < NB; i++) {
        const int prow = o + i;
        if (w == 0) rowp[lane] = VP(prow, lane);
        const int pi = ((i & ~1) >> 1) + w;
        if (pi < 16) {
            const int ca = 2 * pi;
            ull acc = 0ull;
            #pragma unroll 2
            for (int t = prow + lane; t < TN; t += 32) {
                float vi = VP(t, i);
                ull pr = *(const ull*)&VP(t, ca);
                acc = fma2(pk2(vi, vi), pr, acc);
            }
            float p0, p1; upk2(acc, p0, p1);
            p0 = wsum(p0); p1 = wsum(p1);
            if (lane == 0) { wred[ca] = p0; wred[ca + 1] = p1; }
        }
        __syncthreads();
        float alpha = rowp[i];
        float s2 = wred[i];
        float xn2 = s2 - alpha * alpha;
        float tau, sc, beta;
        if (xn2 <= 0.f) { tau = 0.f; sc = 0.f; beta = alpha; }
        else {
            beta = -copysignf(sqrtf(s2), alpha);
            tau  = (beta - alpha) / beta;
            sc   = 1.f / (alpha - beta);
        }
        if (tid == 0) { taus[i] = tau; betas[i] = beta; }
        if (w == 0) {
            float cjp  = rowp[lane];
            float coef = tau * (cjp + (wred[lane] - alpha * cjp) * sc);
            ncoefs[lane] = -coef;
            float nv = (lane == i) ? 1.f : cjp - coef;
            if (lane >= i) VP(prow, lane) = nv;
        }
        __syncthreads();
        int t = prow + 1 + tid;
        if (t < TN) {
            float* vr = Vp + (size_t)t * VS;
            float xt = vr[i];
            float vt = xt * sc;
            vr[i] = vt;
            int j = i + 1;
            if (j < NB) {
                if (j & 1) { vr[j] = fmaf(ncoefs[j], vt, vr[j]); j++; }
                ull vt2 = pk2(vt, vt);
                for (; j < NB; j += 2) {
                    ull nc  = *(const ull*)&ncoefs[j];
                    ull cur = *(const ull*)&vr[j];
                    *(ull*)&vr[j] = fma2(vt2, nc, cur);
                }
            }
        }
        __syncthreads();
    }
}

__device__ void build_T(const float* Vp, float* B, float* Tp, const float* taus,
                        int o, int tid)
{
    const int lane = tid & 31, w = tid >> 5;
    for (int i = 1; i < NB; i++) {
        for (int j = w; j < i; j += 16) {
            float p = 0.f;
            for (int t = o + i + lane; t < TN; t += 32)
                p += VP(t, j) * VP(t, i);
            p = wsum(p);
            if (lane == 0) B[j * 32 + i] = p;
        }
    }
    __syncthreads();
    if (w == 0) {
        for (int i = 0; i < NB; i++) {
            float ti = taus[i];
            float a = 0.f;
            for (int k = 0; k < i; k++)
                a += Tp[lane * 33 + k] * B[k * 32 + i];
            float tv = (lane < i) ? -ti * a : (lane == i ? ti : 0.f);
            Tp[lane * 33 + i] = tv;
            __syncwarp();
        }
    }
    __syncthreads();
}

// SMEM (floats): Vp 17408 | Tp 1056 | Wm 3072 | Wm2 3840 | taus 32 | betas 32 | wred 32 | rowp 32 | ncoefs 32 = 25536
// Phase 2 overlay: Rsm 128x130 (16640) | rd 128
// Phase 3 overlay: Rg 128x132 (16896)  | Ys 128x66 (8448) -> 25344
#define SM_FLOATS 25536
#define SM_BYTES  (SM_FLOATS * 4)

__global__ __launch_bounds__(512, 2) void qr_kernel(float* __restrict__ Yq)
{
    extern __shared__ float sm[];
    float* Vp     = sm;                 // 17408
    float* Tp     = Vp + 17408;         // 1056
    float* Wm     = Tp + 1056;          // 3072
    float* Wm2    = Wm + 3072;          // 3840 (also GEMM1 double-buffer + build_T B)
    float* taus   = Wm2 + 3840;         // 32
    float* betas  = taus + 32;          // 32
    float* wred   = betas + 32;         // 32
    float* rowp   = wred + 32;          // 32
    float* ncoefs = rowp + 32;          // 32

    const int b = blockIdx.x;
    float* G = g_scratch + (size_t)b * TN * FN;
    float* Y = Yq + (size_t)b * TN * FN;
    const int tid = threadIdx.x;
    const int lane = tid & 31, w = tid >> 5;

    // ---------------- geqrf (blocked; p=0 reads Y, writes G) ----------------
    for (int p = 0; p < 4; p++) {
        const int o = p * 32;
        const float* Gsrc = (p == 0) ? Y : G;
        for (int t = o + w; t < TN; t += 16)
            VP(t, lane) = Gsrc[(size_t)t * FN + o + lane];
        __syncthreads();
        panel_factor(Vp, taus, betas, wred, rowp, ncoefs, o, tid);
        for (int pos = tid; pos < 32 * 32; pos += 512) {
            int r = pos >> 5, i = pos & 31;
            float val = (r < i) ? VP(o + r, i) : (r == i ? betas[i] : 0.f);
            G[(size_t)(o + r) * FN + o + i] = val;
        }
        __syncthreads();
        if (p < 3) {
            for (int pos = tid; pos < 32 * 32; pos += 512) {
                int i = pos >> 5, r = pos & 31;
                if (r < i) VP(o + r, i) = 0.f;
            }
            __syncthreads();
            build_T(Vp, Wm2, Tp, taus, o, tid);
            if (p == 0)      block_apply<96>(Y, G, 0,  32, Vp, Tp, Wm, Wm2, tid);
            else if (p == 1) block_apply<64>(G, G, 32, 64, Vp, Tp, Wm, Wm2, tid);
            else             block_apply<32>(G, G, 64, 96, Vp, Tp, Wm, Wm2, tid);
        }
    }
    __syncthreads();

    // ---------------- R^{-1}: saxpy back-substitution, 8 cols ILP per warp ----------------
    float* Rsm = sm;             // 128 x 130 (overlays Vp)
    float* rd  = sm + 16640;     // 128 reciprocals
    for (int e = tid; e < 128 * 128; e += 512) {
        int r = e >> 7, c = e & 127;
        Rsm[r * 130 + c] = G[(size_t)r * FN + c];
    }
    __syncthreads();
    if (tid < 128) rd[tid] = 1.f / Rsm[tid * 130 + tid];
    __syncthreads();

    float xr[8][4];   // column c = w + 16m, row lane + 32q
    #pragma unroll
    for (int m = 0; m < 8; m++)
        #pragma unroll
        for (int q = 0; q < 4; q++) xr[m][q] = 0.f;

    #pragma unroll
    for (int q = 3; q >= 0; q--) {
        for (int kk = 31; kk >= 0; kk--) {
            const int k = q * 32 + kk;
            const float rk = rd[k];
            float rc[4];
            #pragma unroll
            for (int qq = 0; qq <= q; qq++)
                rc[qq] = Rsm[(lane + 32 * qq) * 130 + k];
            #pragma unroll
            for (int m = 0; m < 8; m++) {
                const int c = w + (m << 4);
                if (c >= k) {   // warp-uniform
                    float tmp = (k == c) ? rk : -rk * xr[m][q];
                    float xk = __shfl_sync(0xffffffffu, tmp, kk);
                    if (lane == kk) xr[m][q] = xk;
                    #pragma unroll
                    for (int qq = 0; qq < q; qq++)
                        xr[m][qq] = fmaf(rc[qq], xk, xr[m][qq]);
                    if (lane < kk) xr[m][q] = fmaf(rc[q], xk, xr[m][q]);
                }
            }
        }
    }
    __syncthreads();   // all solve reads of Rsm complete

    // ---------------- Rinv -> SMEM (stride-132, 16B-aligned rows) ----------------
    float* Rg = sm;              // 128 x 132 (overlays Rsm/rd)
    float* Ys = sm + 16896;      // 128 x 66
    #pragma unroll
    for (int m = 0; m < 8; m++) {
        int c = w + (m << 4);
        float* dst = Rg + c;
        dst[(size_t)lane * RGS]        = xr[m][0];
        dst[(size_t)(lane + 32) * RGS] = xr[m][1];
        dst[(size_t)(lane + 64) * RGS] = xr[m][2];
        dst[(size_t)(lane + 96) * RGS] = xr[m][3];
    }
    __syncthreads();

    // ---------------- Q = Y * Rinv (8 tiles of 64 rows, 2 rows/thread) ----------------
    const int cA = 4 * w, cB = 124 - 4 * w;
    const int kmaxA = cA + 4, kmaxB = cB + 4;
    const float* RgA = Rg + cA;
    const float* RgB = Rg + cB;

    for (int tile = 0; tile < 8; tile++) {
        const int t0 = tile * 64;
        #pragma unroll
        for (int e = tid; e < 64 * 32; e += 512) {
            int r = e >> 5, g4 = e & 31;
            float4 v = *(const float4*)(Y + (size_t)(t0 + r) * FN + g4 * 4);
            float* dst = Ys + (g4 * 4) * 66 + r;
            dst[0] = v.x; dst[66] = v.y; dst[132] = v.z; dst[198] = v.w;
        }
        __syncthreads();

        ull aA0 = 0ull, aA1 = 0ull, aB0 = 0ull, aB1 = 0ull;   // row lane
        ull bA0 = 0ull, bA1 = 0ull, bB0 = 0ull, bB1 = 0ull;   // row lane+32
        const float* yb0 = Ys + lane;
        const float* yb1 = Ys + lane + 32;
        int k = 0;
        for (; k < kmaxA; k++) {
            float y0 = yb0[k * 66], y1 = yb1[k * 66];
            ull v0 = pk2(y0, y0), v1 = pk2(y1, y1);
            ulonglong2 wa = *(const ulonglong2*)(RgA + k * RGS);
            ulonglong2 wb = *(const ulonglong2*)(RgB + k * RGS);
            aA0 = fma2(v0, wa.x, aA0); aA1 = fma2(v0, wa.y, aA1);
            aB0 = fma2(v0, wb.x, aB0); aB1 = fma2(v0, wb.y, aB1);
            bA0 = fma2(v1, wa.x, bA0); bA1 = fma2(v1, wa.y, bA1);
            bB0 = fma2(v1, wb.x, bB0); bB1 = fma2(v1, wb.y, bB1);
        }
        for (; k < kmaxB; k++) {
            float y0 = yb0[k * 66], y1 = yb1[k * 66];
            ull v0 = pk2(y0, y0), v1 = pk2(y1, y1);
            ulonglong2 wb = *(const ulonglong2*)(RgB + k * RGS);
            aB0 = fma2(v0, wb.x, aB0); aB1 = fma2(v0, wb.y, aB1);
            bB0 = fma2(v1, wb.x, bB0); bB1 = fma2(v1, wb.y, bB1);
        }
        __syncthreads();   // done reading Ys before restage

        float* orow0 = Y + (size_t)(t0 + lane) * FN;
        float* orow1 = Y + (size_t)(t0 + lane + 32) * FN;
        ulonglong2 q;
        q.x = aA0; q.y = aA1; *(ulonglong2*)(orow0 + cA) = q;
        q.x = aB0; q.y = aB1; *(ulonglong2*)(orow0 + cB) = q;
        q.x = bA0; q.y = bA1; *(ulonglong2*)(orow1 + cA) = q;
        q.x = bB0; q.y = bB1; *(ulonglong2*)(orow1 + cB) = q;
    }
}

// ============================================================
extern "C" void kernel_launch(void* const* d_in, const int* in_sizes, int n_in,
                              void* d_out, int out_size)
{
    const float* x    = (const float*)d_in[0];
    const float* W    = (const float*)d_in[1];
    const float* bias = (const float*)d_in[2];
    float* out = (float*)d_out;

    cudaFuncSetAttribute(qr_kernel, cudaFuncAttributeMaxDynamicSharedMemorySize, SM_BYTES);
    cudaFuncSetAttribute(conv_kernel, cudaFuncAttributeMaxDynamicSharedMemorySize, CONV_SM);

    dim3 cgrid(TN / 64, BN);
    conv_kernel<<<cgrid, 256, CONV_SM>>>(x, W, bias, out);   // Y -> d_out only
    qr_kernel<<<BN, 512, SM_BYTES>>>(out);                   // geqrf(Y->G) + Rinv + Q
}